// round 1
// baseline (speedup 1.0000x reference)
#include <cuda_runtime.h>

#define Bb 4
#define Tt 2048
#define Cc 1024
#define Hh 16
#define Dd 64
#define NTOK (Bb*Tt)   // 8192

// Scratch (allocation-free rule: __device__ globals)
__device__ float g_q[Bb*Hh*Tt*Dd];     // [B,H,T,D]
__device__ float g_k[Bb*Hh*Tt*Dd];
__device__ float g_v[Bb*Hh*Tt*Dd];
__device__ float g_ctx[NTOK*Cc];       // [B*T, C]

// ---------------------------------------------------------------------------
// SGEMM: C[M,N] = A[M,K] @ W[K,N] + bias ; K=1024 fixed, BM=BN=128, BK=16,
// 256 threads, 8x8 per thread. MODE 0: scatter into g_q/g_k/g_v (qkv proj,
// N=3072). MODE 1: A is g_ctx, write dense to Cout (out proj, N=1024).
// ---------------------------------------------------------------------------
template<int N, int MODE>
__global__ __launch_bounds__(256) void sgemm_kernel(
    const float* __restrict__ A, const float* __restrict__ W,
    const float* __restrict__ bias, float* __restrict__ Cout)
{
    constexpr int K = 1024, BM = 128, BN = 128, BK = 16;
    __shared__ float As[BK][BM];
    __shared__ float Bs[BK][BN];

    const int tid = threadIdx.x;
    const int bx = blockIdx.x, by = blockIdx.y;
    const int tx = tid & 15, ty = tid >> 4;
    const int row0 = by * BM + ty * 8;
    const int col0 = bx * BN + tx * 8;

    const float* Ap = (MODE == 1) ? (const float*)g_ctx : A;
    const float* Ablk = Ap + (size_t)by * BM * K;
    const float* Wblk = W + bx * BN;

    float acc[8][8];
    #pragma unroll
    for (int i = 0; i < 8; i++)
        #pragma unroll
        for (int j = 0; j < 8; j++) acc[i][j] = 0.f;

    for (int kt = 0; kt < K; kt += BK) {
        // A tile: 128 rows x 16 cols -> transposed into As[k][m]
        #pragma unroll
        for (int l = 0; l < 2; l++) {
            int id = tid + l * 256;          // 0..511 float4 ids
            int r  = id >> 2;                // row 0..127
            int c4 = id & 3;                 // float4 within row
            float4 va = *(const float4*)(Ablk + (size_t)r * K + kt + c4 * 4);
            As[c4*4+0][r] = va.x;
            As[c4*4+1][r] = va.y;
            As[c4*4+2][r] = va.z;
            As[c4*4+3][r] = va.w;
        }
        // W tile: 16 rows x 128 cols
        #pragma unroll
        for (int l = 0; l < 2; l++) {
            int id = tid + l * 256;
            int r  = id >> 5;                // 0..15
            int c4 = id & 31;                // 0..31
            *(float4*)&Bs[r][c4*4] =
                *(const float4*)(Wblk + (size_t)(kt + r) * N + c4 * 4);
        }
        __syncthreads();

        #pragma unroll
        for (int k = 0; k < BK; k++) {
            float a[8], b[8];
            *(float4*)&a[0] = *(float4*)&As[k][ty*8];
            *(float4*)&a[4] = *(float4*)&As[k][ty*8 + 4];
            *(float4*)&b[0] = *(float4*)&Bs[k][tx*8];
            *(float4*)&b[4] = *(float4*)&Bs[k][tx*8 + 4];
            #pragma unroll
            for (int i = 0; i < 8; i++)
                #pragma unroll
                for (int j = 0; j < 8; j++)
                    acc[i][j] = fmaf(a[i], b[j], acc[i][j]);
        }
        __syncthreads();
    }

    #pragma unroll
    for (int i = 0; i < 8; i++) {
        int m = row0 + i;
        #pragma unroll
        for (int j = 0; j < 8; j++) {
            int n = col0 + j;
            float val = acc[i][j] + bias[n];
            if (MODE == 0) {
                int s   = n >> 10;           // 0:q 1:k 2:v
                int rem = n & 1023;
                int hh  = rem >> 6, dd = rem & 63;
                int bi  = m >> 11, t  = m & 2047;
                float* dst = (s == 0) ? g_q : (s == 1) ? g_k : g_v;
                dst[(((bi*Hh) + hh)*Tt + t)*Dd + dd] = val;
            } else {
                Cout[(size_t)m * N + n] = val;
            }
        }
    }
}

// ---------------------------------------------------------------------------
// Causal flash attention, fp32. One thread = one query row (128 rows/block).
// K/V staged in smem as 64x64 tiles; per-thread online softmax; keys
// processed in chunks of 16 to bound register pressure.
// grid = (16 qtiles, 16 heads, 4 batch), 128 threads.
// ---------------------------------------------------------------------------
__global__ __launch_bounds__(128) void attn_kernel()
{
    const int tid = threadIdx.x;
    const int qt  = blockIdx.x;
    const int h   = blockIdx.y;
    const int b   = blockIdx.z;
    const int m   = qt * 128 + tid;          // query row in [0,T)
    const float scale = 0.125f;              // 1/sqrt(64)

    const float* Qb = g_q + ((b*Hh + h) * Tt) * Dd;
    const float* Kb = g_k + ((b*Hh + h) * Tt) * Dd;
    const float* Vb = g_v + ((b*Hh + h) * Tt) * Dd;

    __shared__ float Ksh[64][64];
    __shared__ float Vsh[64][64];

    float q[64];
    #pragma unroll
    for (int i = 0; i < 16; i++) {
        float4 v4 = *(const float4*)(Qb + m * Dd + i * 4);
        q[i*4+0] = v4.x; q[i*4+1] = v4.y; q[i*4+2] = v4.z; q[i*4+3] = v4.w;
    }

    float mi = -1e30f, li = 0.f;
    float acc[64];
    #pragma unroll
    for (int d = 0; d < 64; d++) acc[d] = 0.f;

    const int ntiles = 2 * qt + 2;           // ceil((qt*128+127+1)/64)

    for (int kt = 0; kt < ntiles; kt++) {
        // stage K/V tile: 64 rows x 64 floats = 1024 float4; 8 per thread
        #pragma unroll
        for (int i = 0; i < 8; i++) {
            int idx = tid + i * 128;
            int r = idx >> 4, c = idx & 15;
            ((float4*)Ksh)[idx] = *(const float4*)(Kb + (kt*64 + r) * Dd + c*4);
            ((float4*)Vsh)[idx] = *(const float4*)(Vb + (kt*64 + r) * Dd + c*4);
        }
        __syncthreads();

        #pragma unroll
        for (int ch = 0; ch < 4; ch++) {
            float s[16];
            #pragma unroll
            for (int j = 0; j < 16; j++) {
                const int jj = ch * 16 + j;
                float sv = 0.f;
                #pragma unroll
                for (int d4 = 0; d4 < 16; d4++) {
                    float4 kv = *(const float4*)&Ksh[jj][d4*4];
                    sv = fmaf(q[d4*4+0], kv.x, sv);
                    sv = fmaf(q[d4*4+1], kv.y, sv);
                    sv = fmaf(q[d4*4+2], kv.z, sv);
                    sv = fmaf(q[d4*4+3], kv.w, sv);
                }
                const int kg = kt * 64 + jj;
                s[j] = (kg <= m) ? sv * scale : -1e30f;
            }
            // online softmax update for this 16-key chunk
            float cm = mi;
            #pragma unroll
            for (int j = 0; j < 16; j++) cm = fmaxf(cm, s[j]);
            const float f = __expf(mi - cm);
            mi = cm;
            li *= f;
            #pragma unroll
            for (int d = 0; d < 64; d++) acc[d] *= f;
            #pragma unroll
            for (int j = 0; j < 16; j++) {
                const float p = __expf(s[j] - mi);
                li += p;
                const int jj = ch * 16 + j;
                #pragma unroll
                for (int d4 = 0; d4 < 16; d4++) {
                    float4 vv = *(const float4*)&Vsh[jj][d4*4];
                    acc[d4*4+0] = fmaf(p, vv.x, acc[d4*4+0]);
                    acc[d4*4+1] = fmaf(p, vv.y, acc[d4*4+1]);
                    acc[d4*4+2] = fmaf(p, vv.z, acc[d4*4+2]);
                    acc[d4*4+3] = fmaf(p, vv.w, acc[d4*4+3]);
                }
            }
        }
        __syncthreads();
    }

    const float inv = 1.f / li;
    float* out = g_ctx + (size_t)(b * Tt + m) * Cc + h * Dd;
    #pragma unroll
    for (int d4 = 0; d4 < 16; d4++) {
        float4 o;
        o.x = acc[d4*4+0] * inv;
        o.y = acc[d4*4+1] * inv;
        o.z = acc[d4*4+2] * inv;
        o.w = acc[d4*4+3] * inv;
        *(float4*)(out + d4*4) = o;
    }
}

// ---------------------------------------------------------------------------
extern "C" void kernel_launch(void* const* d_in, const int* in_sizes, int n_in,
                              void* d_out, int out_size)
{
    const float* x     = (const float*)d_in[0];  // [4,2048,1024]
    const float* w_qkv = (const float*)d_in[1];  // [1024,3072]
    const float* b_qkv = (const float*)d_in[2];  // [3072]
    const float* w_out = (const float*)d_in[3];  // [1024,1024]
    const float* b_out = (const float*)d_in[4];  // [1024]
    float* out = (float*)d_out;                  // [4,2048,1024]

    // 1) QKV projection: [8192,1024]@[1024,3072]+b -> scatter to g_q/g_k/g_v
    {
        dim3 grid(3072 / 128, NTOK / 128);
        sgemm_kernel<3072, 0><<<grid, 256>>>(x, w_qkv, b_qkv, nullptr);
    }
    // 2) Causal flash attention -> g_ctx
    {
        dim3 grid(Tt / 128, Hh, Bb);
        attn_kernel<<<grid, 128>>>();
    }
    // 3) Output projection: g_ctx @ w_out + b_out -> out
    {
        dim3 grid(1024 / 128, NTOK / 128);
        sgemm_kernel<1024, 1><<<grid, 256>>>(nullptr, w_out, b_out, out);
    }
}

// round 3
// speedup vs baseline: 1.2590x; 1.2590x over previous
#include <cuda_runtime.h>
#include <cuda_bf16.h>
#include <cstdint>

#define Bb 4
#define Tt 2048
#define Cc 1024
#define Hh 16
#define Dd 64
#define NTOK (Bb*Tt)   // 8192

// ---------------------------------------------------------------------------
// Scratch (__device__ globals: allocation-free rule)
// ---------------------------------------------------------------------------
__device__ float g_q[Bb*Hh*Tt*Dd];
__device__ float g_k[Bb*Hh*Tt*Dd];
__device__ float g_v[Bb*Hh*Tt*Dd];
__device__ float g_ctx[(size_t)NTOK*Cc];
__device__ __nv_bfloat16 g_wqkv_hi[3072*1024];
__device__ __nv_bfloat16 g_wqkv_lo[3072*1024];
__device__ __nv_bfloat16 g_wout_hi[1024*1024];
__device__ __nv_bfloat16 g_wout_lo[1024*1024];

// ---------------------------------------------------------------------------
// mma.sync helpers (sm_80-class path; works in virtual compute_103)
// ---------------------------------------------------------------------------
__device__ __forceinline__ uint32_t smem_u32(const void* p) {
    uint32_t a;
    asm("{ .reg .u64 t; cvta.to.shared.u64 t, %1; cvt.u32.u64 %0, t; }"
        : "=r"(a) : "l"(p));
    return a;
}
__device__ __forceinline__ void ldsm_x4(uint32_t addr, uint32_t& r0, uint32_t& r1,
                                        uint32_t& r2, uint32_t& r3) {
    asm volatile("ldmatrix.sync.aligned.m8n8.x4.shared.b16 {%0,%1,%2,%3}, [%4];"
                 : "=r"(r0), "=r"(r1), "=r"(r2), "=r"(r3) : "r"(addr));
}
__device__ __forceinline__ void mma_bf16(float* d, const uint32_t* a, const uint32_t* b) {
    asm volatile(
        "mma.sync.aligned.m16n8k16.row.col.f32.bf16.bf16.f32 "
        "{%0,%1,%2,%3}, {%4,%5,%6,%7}, {%8,%9}, {%0,%1,%2,%3};"
        : "+f"(d[0]), "+f"(d[1]), "+f"(d[2]), "+f"(d[3])
        : "r"(a[0]), "r"(a[1]), "r"(a[2]), "r"(a[3]), "r"(b[0]), "r"(b[1]));
}

// ---------------------------------------------------------------------------
// Weight transpose + bf16 hi/lo split: w[1024][N] -> Wt_hi/lo[N][1024]
// MODE 0: w_qkv (N=3072)   MODE 1: w_out (N=1024)
// ---------------------------------------------------------------------------
template<int MODE>
__global__ __launch_bounds__(256) void conv_w_kernel(const float* __restrict__ w)
{
    constexpr int N = (MODE == 0) ? 3072 : 1024;
    __nv_bfloat16* th = (MODE == 0) ? g_wqkv_hi : g_wout_hi;
    __nv_bfloat16* tl = (MODE == 0) ? g_wqkv_lo : g_wout_lo;
    __shared__ float tile[32][33];
    const int n0 = blockIdx.x * 32, k0 = blockIdx.y * 32;
    const int tx = threadIdx.x, ty = threadIdx.y;   // 32 x 8
    #pragma unroll
    for (int i = 0; i < 4; i++) {
        int k = ty + i * 8;
        tile[k][tx] = w[(size_t)(k0 + k) * N + n0 + tx];
    }
    __syncthreads();
    #pragma unroll
    for (int i = 0; i < 4; i++) {
        int r = ty + i * 8;                 // n-local
        float v = tile[tx][r];              // (k0+tx, n0+r)
        __nv_bfloat16 h = __float2bfloat16_rn(v);
        float l = v - __bfloat162float(h);
        size_t o = (size_t)(n0 + r) * 1024 + k0 + tx;
        th[o] = h;
        tl[o] = __float2bfloat16_rn(l);
    }
}

// ---------------------------------------------------------------------------
// HMMA GEMM: C[M,N] = A[M,1024] @ Wt^T + bias, split-bf16 3-term
// (Ahi@Bhi + Alo@Bhi + Ahi@Blo), fp32 accumulate in registers.
// CTA 128x128, 8 warps (2Mx4N), warp tile 64x32 (4x4 mma tiles of 16x8).
// K-chunk 32 (two k16 mma steps). smem stride 40 bf16 (conflict-free ldmatrix).
// MODE 0: A=x, scatter C to g_q/g_k/g_v.  MODE 1: A=g_ctx, dense out.
// ---------------------------------------------------------------------------
template<int N, int MODE>
__global__ __launch_bounds__(256, 2) void tgemm_kernel(
    const float* __restrict__ Ax, const float* __restrict__ bias,
    float* __restrict__ Cout)
{
    constexpr int LDS = 40;                 // padded row stride (bf16)
    __shared__ __nv_bfloat16 AshH[128*LDS], AshL[128*LDS];
    __shared__ __nv_bfloat16 BshH[128*LDS], BshL[128*LDS];

    const __nv_bfloat16* BtH = (MODE == 0) ? g_wqkv_hi : g_wout_hi;
    const __nv_bfloat16* BtL = (MODE == 0) ? g_wqkv_lo : g_wout_lo;
    const float* A = (MODE == 0) ? Ax : (const float*)g_ctx;

    const int tid  = threadIdx.x;
    const int wid  = tid >> 5, lane = tid & 31;
    const int wm   = (wid >> 2) * 64;       // warp m offset (0 / 64)
    const int wn   = (wid & 3) * 32;        // warp n offset
    const int sub  = lane >> 3;             // ldmatrix matrix id
    const int l7   = lane & 7;
    const int n0   = blockIdx.x * 128, m0 = blockIdx.y * 128;

    const uint32_t aHB = smem_u32(AshH), aLB = smem_u32(AshL);
    const uint32_t bHB = smem_u32(BshH), bLB = smem_u32(BshL);
    // per-thread ldmatrix row/col components
    const int fr = (sub & 1) * 8 + l7;      // row within 16-row group
    const int fc = (sub >> 1) * 8;          // col (k) within 16

    float acc[4][4][4];
    #pragma unroll
    for (int i = 0; i < 4; i++)
        #pragma unroll
        for (int j = 0; j < 4; j++)
            #pragma unroll
            for (int c = 0; c < 4; c++) acc[i][j][c] = 0.f;

    for (int ch = 0; ch < 32; ch++) {
        const int k0 = ch * 32;
        // --- A tile: 128x32 fp32 -> bf16 hi/lo ---
        #pragma unroll
        for (int i = 0; i < 4; i++) {
            int id = tid + i * 256;
            int r = id >> 3, c4 = id & 7;
            float4 v = __ldg((const float4*)(A + (size_t)(m0 + r) * 1024 + k0 + c4 * 4));
            __nv_bfloat16 hx = __float2bfloat16_rn(v.x);
            __nv_bfloat16 hy = __float2bfloat16_rn(v.y);
            __nv_bfloat16 hz = __float2bfloat16_rn(v.z);
            __nv_bfloat16 hw = __float2bfloat16_rn(v.w);
            __nv_bfloat162 h01{hx, hy}, h23{hz, hw};
            __nv_bfloat162 l01, l23;
            l01.x = __float2bfloat16_rn(v.x - __bfloat162float(hx));
            l01.y = __float2bfloat16_rn(v.y - __bfloat162float(hy));
            l23.x = __float2bfloat16_rn(v.z - __bfloat162float(hz));
            l23.y = __float2bfloat16_rn(v.w - __bfloat162float(hw));
            uint2 uh{*(uint32_t*)&h01, *(uint32_t*)&h23};
            uint2 ul{*(uint32_t*)&l01, *(uint32_t*)&l23};
            *(uint2*)&AshH[r * LDS + c4 * 4] = uh;
            *(uint2*)&AshL[r * LDS + c4 * 4] = ul;
        }
        // --- B tiles: 128x32 bf16 hi & lo ---
        #pragma unroll
        for (int i = 0; i < 2; i++) {
            int id = tid + i * 256;
            int r = id >> 2, c = id & 3;
            size_t src = (size_t)(n0 + r) * 1024 + k0 + c * 8;
            *(float4*)&BshH[r * LDS + c * 8] = __ldg((const float4*)(BtH + src));
            *(float4*)&BshL[r * LDS + c * 8] = __ldg((const float4*)(BtL + src));
        }
        __syncthreads();

        #pragma unroll
        for (int half = 0; half < 2; half++) {
            const int kk = half * 16;
            uint32_t aH[4][4], aL[4][4], bH[4][2], bL[4][2];
            #pragma unroll
            for (int mt = 0; mt < 4; mt++) {
                uint32_t off = (uint32_t)((wm + mt * 16 + fr) * LDS + kk + fc) * 2;
                ldsm_x4(aHB + off, aH[mt][0], aH[mt][1], aH[mt][2], aH[mt][3]);
                ldsm_x4(aLB + off, aL[mt][0], aL[mt][1], aL[mt][2], aL[mt][3]);
            }
            #pragma unroll
            for (int np = 0; np < 2; np++) {
                uint32_t off = (uint32_t)((wn + np * 16 + fr) * LDS + kk + fc) * 2;
                uint32_t r0, r1, r2, r3;
                ldsm_x4(bHB + off, r0, r1, r2, r3);
                bH[np*2+0][0] = r0; bH[np*2+0][1] = r2;
                bH[np*2+1][0] = r1; bH[np*2+1][1] = r3;
                ldsm_x4(bLB + off, r0, r1, r2, r3);
                bL[np*2+0][0] = r0; bL[np*2+0][1] = r2;
                bL[np*2+1][0] = r1; bL[np*2+1][1] = r3;
            }
            #pragma unroll
            for (int mt = 0; mt < 4; mt++)
                #pragma unroll
                for (int nt = 0; nt < 4; nt++) {
                    mma_bf16(acc[mt][nt], aH[mt], bH[nt]);
                    mma_bf16(acc[mt][nt], aL[mt], bH[nt]);
                    mma_bf16(acc[mt][nt], aH[mt], bL[nt]);
                }
        }
        __syncthreads();
    }

    // --- Epilogue: fragment layout -> global (float2 stores) ---
    const int g = lane >> 2, tg = lane & 3;
    #pragma unroll
    for (int mt = 0; mt < 4; mt++)
        #pragma unroll
        for (int nt = 0; nt < 4; nt++) {
            int n = n0 + wn + nt * 8 + tg * 2;
            float bx = __ldg(bias + n), by = __ldg(bias + n + 1);
            #pragma unroll
            for (int hrow = 0; hrow < 2; hrow++) {
                int m = m0 + wm + mt * 16 + g + hrow * 8;
                float2 o;
                o.x = acc[mt][nt][hrow * 2 + 0] + bx;
                o.y = acc[mt][nt][hrow * 2 + 1] + by;
                if (MODE == 0) {
                    int s   = n >> 10;
                    int rem = n & 1023;
                    int hh  = rem >> 6, dd = rem & 63;
                    int bi  = m >> 11, t = m & 2047;
                    float* dst = (s == 0) ? g_q : (s == 1) ? g_k : g_v;
                    *(float2*)(dst + (((size_t)(bi * Hh + hh)) * Tt + t) * Dd + dd) = o;
                } else {
                    *(float2*)(Cout + (size_t)m * N + n) = o;
                }
            }
        }
}

// ---------------------------------------------------------------------------
// Causal flash attention, fp32 SIMT (unchanged from R1 baseline).
// ---------------------------------------------------------------------------
__global__ __launch_bounds__(128) void attn_kernel()
{
    const int tid = threadIdx.x;
    const int qt  = blockIdx.x;
    const int h   = blockIdx.y;
    const int b   = blockIdx.z;
    const int m   = qt * 128 + tid;
    const float scale = 0.125f;

    const float* Qb = g_q + ((b*Hh + h) * Tt) * Dd;
    const float* Kb = g_k + ((b*Hh + h) * Tt) * Dd;
    const float* Vb = g_v + ((b*Hh + h) * Tt) * Dd;

    __shared__ float Ksh[64][64];
    __shared__ float Vsh[64][64];

    float q[64];
    #pragma unroll
    for (int i = 0; i < 16; i++) {
        float4 v4 = *(const float4*)(Qb + m * Dd + i * 4);
        q[i*4+0] = v4.x; q[i*4+1] = v4.y; q[i*4+2] = v4.z; q[i*4+3] = v4.w;
    }

    float mi = -1e30f, li = 0.f;
    float acc[64];
    #pragma unroll
    for (int d = 0; d < 64; d++) acc[d] = 0.f;

    const int ntiles = 2 * qt + 2;

    for (int kt = 0; kt < ntiles; kt++) {
        #pragma unroll
        for (int i = 0; i < 8; i++) {
            int idx = tid + i * 128;
            int r = idx >> 4, c = idx & 15;
            ((float4*)Ksh)[idx] = *(const float4*)(Kb + (kt*64 + r) * Dd + c*4);
            ((float4*)Vsh)[idx] = *(const float4*)(Vb + (kt*64 + r) * Dd + c*4);
        }
        __syncthreads();

        #pragma unroll
        for (int ch = 0; ch < 4; ch++) {
            float s[16];
            #pragma unroll
            for (int j = 0; j < 16; j++) {
                const int jj = ch * 16 + j;
                float sv = 0.f;
                #pragma unroll
                for (int d4 = 0; d4 < 16; d4++) {
                    float4 kv = *(const float4*)&Ksh[jj][d4*4];
                    sv = fmaf(q[d4*4+0], kv.x, sv);
                    sv = fmaf(q[d4*4+1], kv.y, sv);
                    sv = fmaf(q[d4*4+2], kv.z, sv);
                    sv = fmaf(q[d4*4+3], kv.w, sv);
                }
                const int kg = kt * 64 + jj;
                s[j] = (kg <= m) ? sv * scale : -1e30f;
            }
            float cm = mi;
            #pragma unroll
            for (int j = 0; j < 16; j++) cm = fmaxf(cm, s[j]);
            const float f = __expf(mi - cm);
            mi = cm;
            li *= f;
            #pragma unroll
            for (int d = 0; d < 64; d++) acc[d] *= f;
            #pragma unroll
            for (int j = 0; j < 16; j++) {
                const float p = __expf(s[j] - mi);
                li += p;
                const int jj = ch * 16 + j;
                #pragma unroll
                for (int d4 = 0; d4 < 16; d4++) {
                    float4 vv = *(const float4*)&Vsh[jj][d4*4];
                    acc[d4*4+0] = fmaf(p, vv.x, acc[d4*4+0]);
                    acc[d4*4+1] = fmaf(p, vv.y, acc[d4*4+1]);
                    acc[d4*4+2] = fmaf(p, vv.z, acc[d4*4+2]);
                    acc[d4*4+3] = fmaf(p, vv.w, acc[d4*4+3]);
                }
            }
        }
        __syncthreads();
    }

    const float inv = 1.f / li;
    float* out = g_ctx + (size_t)(b * Tt + m) * Cc + h * Dd;
    #pragma unroll
    for (int d4 = 0; d4 < 16; d4++) {
        float4 o;
        o.x = acc[d4*4+0] * inv;
        o.y = acc[d4*4+1] * inv;
        o.z = acc[d4*4+2] * inv;
        o.w = acc[d4*4+3] * inv;
        *(float4*)(out + d4*4) = o;
    }
}

// ---------------------------------------------------------------------------
extern "C" void kernel_launch(void* const* d_in, const int* in_sizes, int n_in,
                              void* d_out, int out_size)
{
    const float* x     = (const float*)d_in[0];
    const float* w_qkv = (const float*)d_in[1];
    const float* b_qkv = (const float*)d_in[2];
    const float* w_out = (const float*)d_in[3];
    const float* b_out = (const float*)d_in[4];
    float* out = (float*)d_out;

    // 0) Weight transpose + hi/lo split
    {
        dim3 blk(32, 8);
        conv_w_kernel<0><<<dim3(3072 / 32, 1024 / 32), blk>>>(w_qkv);
        conv_w_kernel<1><<<dim3(1024 / 32, 1024 / 32), blk>>>(w_out);
    }
    // 1) QKV projection (HMMA) -> g_q/g_k/g_v
    tgemm_kernel<3072, 0><<<dim3(3072 / 128, NTOK / 128), 256>>>(x, b_qkv, nullptr);
    // 2) Causal flash attention -> g_ctx
    attn_kernel<<<dim3(Tt / 128, Hh, Bb), 128>>>();
    // 3) Output projection (HMMA) -> out
    tgemm_kernel<1024, 1><<<dim3(1024 / 128, NTOK / 128), 256>>>(nullptr, b_out, out);
}

// round 4
// speedup vs baseline: 3.9171x; 3.1114x over previous
#include <cuda_runtime.h>
#include <cuda_bf16.h>
#include <cstdint>

#define Bb 4
#define Tt 2048
#define Cc 1024
#define Hh 16
#define Dd 64
#define NTOK (Bb*Tt)   // 8192

// ---------------------------------------------------------------------------
// Scratch (__device__ globals: allocation-free rule)
// ---------------------------------------------------------------------------
__device__ float g_ctx[(size_t)NTOK*Cc];
__device__ __nv_bfloat16 g_qh[Bb*Hh*Tt*Dd], g_ql[Bb*Hh*Tt*Dd];
__device__ __nv_bfloat16 g_kh[Bb*Hh*Tt*Dd], g_kl[Bb*Hh*Tt*Dd];
__device__ __nv_bfloat16 g_vh[Bb*Hh*Tt*Dd], g_vl[Bb*Hh*Tt*Dd];
__device__ __nv_bfloat16 g_wqkv_hi[3072*1024];
__device__ __nv_bfloat16 g_wqkv_lo[3072*1024];
__device__ __nv_bfloat16 g_wout_hi[1024*1024];
__device__ __nv_bfloat16 g_wout_lo[1024*1024];

// ---------------------------------------------------------------------------
// mma.sync helpers
// ---------------------------------------------------------------------------
__device__ __forceinline__ uint32_t smem_u32(const void* p) {
    uint32_t a;
    asm("{ .reg .u64 t; cvta.to.shared.u64 t, %1; cvt.u32.u64 %0, t; }"
        : "=r"(a) : "l"(p));
    return a;
}
__device__ __forceinline__ void ldsm_x4(uint32_t addr, uint32_t& r0, uint32_t& r1,
                                        uint32_t& r2, uint32_t& r3) {
    asm volatile("ldmatrix.sync.aligned.m8n8.x4.shared.b16 {%0,%1,%2,%3}, [%4];"
                 : "=r"(r0), "=r"(r1), "=r"(r2), "=r"(r3) : "r"(addr));
}
__device__ __forceinline__ void ldsm_x4_t(uint32_t addr, uint32_t& r0, uint32_t& r1,
                                          uint32_t& r2, uint32_t& r3) {
    asm volatile("ldmatrix.sync.aligned.m8n8.x4.trans.shared.b16 {%0,%1,%2,%3}, [%4];"
                 : "=r"(r0), "=r"(r1), "=r"(r2), "=r"(r3) : "r"(addr));
}
__device__ __forceinline__ void mma_bf16(float* d, const uint32_t* a, const uint32_t* b) {
    asm volatile(
        "mma.sync.aligned.m16n8k16.row.col.f32.bf16.bf16.f32 "
        "{%0,%1,%2,%3}, {%4,%5,%6,%7}, {%8,%9}, {%0,%1,%2,%3};"
        : "+f"(d[0]), "+f"(d[1]), "+f"(d[2]), "+f"(d[3])
        : "r"(a[0]), "r"(a[1]), "r"(a[2]), "r"(a[3]), "r"(b[0]), "r"(b[1]));
}
__device__ __forceinline__ uint32_t pack_hilo(float x, float y, uint32_t& lo) {
    __nv_bfloat16 hx = __float2bfloat16_rn(x), hy = __float2bfloat16_rn(y);
    __nv_bfloat162 h; h.x = hx; h.y = hy;
    __nv_bfloat162 l;
    l.x = __float2bfloat16_rn(x - __bfloat162float(hx));
    l.y = __float2bfloat16_rn(y - __bfloat162float(hy));
    lo = *(uint32_t*)&l;
    return *(uint32_t*)&h;
}

// ---------------------------------------------------------------------------
// Weight transpose + bf16 hi/lo split: w[1024][N] -> Wt_hi/lo[N][1024]
// ---------------------------------------------------------------------------
template<int MODE>
__global__ __launch_bounds__(256) void conv_w_kernel(const float* __restrict__ w)
{
    constexpr int N = (MODE == 0) ? 3072 : 1024;
    __nv_bfloat16* th = (MODE == 0) ? g_wqkv_hi : g_wout_hi;
    __nv_bfloat16* tl = (MODE == 0) ? g_wqkv_lo : g_wout_lo;
    __shared__ float tile[32][33];
    const int n0 = blockIdx.x * 32, k0 = blockIdx.y * 32;
    const int tx = threadIdx.x, ty = threadIdx.y;
    #pragma unroll
    for (int i = 0; i < 4; i++) {
        int k = ty + i * 8;
        tile[k][tx] = w[(size_t)(k0 + k) * N + n0 + tx];
    }
    __syncthreads();
    #pragma unroll
    for (int i = 0; i < 4; i++) {
        int r = ty + i * 8;
        float v = tile[tx][r];
        __nv_bfloat16 h = __float2bfloat16_rn(v);
        float l = v - __bfloat162float(h);
        size_t o = (size_t)(n0 + r) * 1024 + k0 + tx;
        th[o] = h;
        tl[o] = __float2bfloat16_rn(l);
    }
}

// ---------------------------------------------------------------------------
// HMMA GEMM (as R3). MODE 0: write q/k/v as bf16 hi/lo (q pre-scaled).
// MODE 1: A = g_ctx, dense fp32 out.
// ---------------------------------------------------------------------------
template<int N, int MODE>
__global__ __launch_bounds__(256, 2) void tgemm_kernel(
    const float* __restrict__ Ax, const float* __restrict__ bias,
    float* __restrict__ Cout)
{
    constexpr int LDS = 40;
    __shared__ __nv_bfloat16 AshH[128*LDS], AshL[128*LDS];
    __shared__ __nv_bfloat16 BshH[128*LDS], BshL[128*LDS];

    const __nv_bfloat16* BtH = (MODE == 0) ? g_wqkv_hi : g_wout_hi;
    const __nv_bfloat16* BtL = (MODE == 0) ? g_wqkv_lo : g_wout_lo;
    const float* A = (MODE == 0) ? Ax : (const float*)g_ctx;

    const int tid  = threadIdx.x;
    const int wid  = tid >> 5, lane = tid & 31;
    const int wm   = (wid >> 2) * 64;
    const int wn   = (wid & 3) * 32;
    const int lr   = lane & 15, lc = (lane >> 4) * 8;
    const int n0   = blockIdx.x * 128, m0 = blockIdx.y * 128;

    const uint32_t aHB = smem_u32(AshH), aLB = smem_u32(AshL);
    const uint32_t bHB = smem_u32(BshH), bLB = smem_u32(BshL);

    float acc[4][4][4];
    #pragma unroll
    for (int i = 0; i < 4; i++)
        #pragma unroll
        for (int j = 0; j < 4; j++)
            #pragma unroll
            for (int c = 0; c < 4; c++) acc[i][j][c] = 0.f;

    for (int ch = 0; ch < 32; ch++) {
        const int k0 = ch * 32;
        #pragma unroll
        for (int i = 0; i < 4; i++) {
            int id = tid + i * 256;
            int r = id >> 3, c4 = id & 7;
            float4 v = __ldg((const float4*)(A + (size_t)(m0 + r) * 1024 + k0 + c4 * 4));
            uint32_t l01, l23;
            uint32_t h01 = pack_hilo(v.x, v.y, l01);
            uint32_t h23 = pack_hilo(v.z, v.w, l23);
            uint2 uh; uh.x = h01; uh.y = h23;
            uint2 ul; ul.x = l01; ul.y = l23;
            *(uint2*)&AshH[r * LDS + c4 * 4] = uh;
            *(uint2*)&AshL[r * LDS + c4 * 4] = ul;
        }
        #pragma unroll
        for (int i = 0; i < 2; i++) {
            int id = tid + i * 256;
            int r = id >> 2, c = id & 3;
            size_t src = (size_t)(n0 + r) * 1024 + k0 + c * 8;
            *(float4*)&BshH[r * LDS + c * 8] = __ldg((const float4*)(BtH + src));
            *(float4*)&BshL[r * LDS + c * 8] = __ldg((const float4*)(BtL + src));
        }
        __syncthreads();

        #pragma unroll
        for (int half = 0; half < 2; half++) {
            const int kk = half * 16;
            uint32_t aH[4][4], aL[4][4], bH[4][2], bL[4][2];
            #pragma unroll
            for (int mt = 0; mt < 4; mt++) {
                uint32_t off = (uint32_t)((wm + mt * 16 + lr) * LDS + kk + lc) * 2;
                ldsm_x4(aHB + off, aH[mt][0], aH[mt][1], aH[mt][2], aH[mt][3]);
                ldsm_x4(aLB + off, aL[mt][0], aL[mt][1], aL[mt][2], aL[mt][3]);
            }
            #pragma unroll
            for (int np = 0; np < 2; np++) {
                uint32_t off = (uint32_t)((wn + np * 16 + lr) * LDS + kk + lc) * 2;
                uint32_t r0, r1, r2, r3;
                ldsm_x4(bHB + off, r0, r1, r2, r3);
                bH[np*2+0][0] = r0; bH[np*2+0][1] = r2;
                bH[np*2+1][0] = r1; bH[np*2+1][1] = r3;
                ldsm_x4(bLB + off, r0, r1, r2, r3);
                bL[np*2+0][0] = r0; bL[np*2+0][1] = r2;
                bL[np*2+1][0] = r1; bL[np*2+1][1] = r3;
            }
            #pragma unroll
            for (int mt = 0; mt < 4; mt++)
                #pragma unroll
                for (int nt = 0; nt < 4; nt++) {
                    mma_bf16(acc[mt][nt], aH[mt], bH[nt]);
                    mma_bf16(acc[mt][nt], aL[mt], bH[nt]);
                    mma_bf16(acc[mt][nt], aH[mt], bL[nt]);
                }
        }
        __syncthreads();
    }

    const int g = lane >> 2, tg = lane & 3;
    #pragma unroll
    for (int mt = 0; mt < 4; mt++)
        #pragma unroll
        for (int nt = 0; nt < 4; nt++) {
            int n = n0 + wn + nt * 8 + tg * 2;
            float bx = __ldg(bias + n), by = __ldg(bias + n + 1);
            #pragma unroll
            for (int hrow = 0; hrow < 2; hrow++) {
                int m = m0 + wm + mt * 16 + g + hrow * 8;
                float vx = acc[mt][nt][hrow * 2 + 0] + bx;
                float vy = acc[mt][nt][hrow * 2 + 1] + by;
                if (MODE == 0) {
                    int s   = n >> 10;
                    int rem = n & 1023;
                    int hh  = rem >> 6, dd = rem & 63;
                    int bi  = m >> 11, t = m & 2047;
                    if (s == 0) { vx *= 0.125f; vy *= 0.125f; }  // q pre-scale
                    uint32_t lo;
                    uint32_t hi = pack_hilo(vx, vy, lo);
                    __nv_bfloat16* dh = (s == 0) ? g_qh : (s == 1) ? g_kh : g_vh;
                    __nv_bfloat16* dl = (s == 0) ? g_ql : (s == 1) ? g_kl : g_vl;
                    size_t off = (((size_t)(bi * Hh + hh)) * Tt + t) * Dd + dd;
                    *(uint32_t*)(dh + off) = hi;
                    *(uint32_t*)(dl + off) = lo;
                } else {
                    float2 o; o.x = vx; o.y = vy;
                    *(float2*)(Cout + (size_t)m * N + n) = o;
                }
            }
        }
}

// ---------------------------------------------------------------------------
// Flash attention via mma.sync, split-bf16 3-term for S and PV.
// CTA: 128 q rows, 4 warps (32 rows each). K/V tiles of 64 keys.
// smem rows padded to 72 bf16 (conflict-free ldmatrix).
// ---------------------------------------------------------------------------
__global__ __launch_bounds__(128, 2) void attn_mma_kernel()
{
    extern __shared__ __nv_bfloat16 sm[];
    __nv_bfloat16* Qh = sm;                 // 128*72
    __nv_bfloat16* Ql = sm + 9216;
    __nv_bfloat16* Kh = sm + 18432;         // 64*72
    __nv_bfloat16* Kl = sm + 23040;
    __nv_bfloat16* Vh = sm + 27648;
    __nv_bfloat16* Vl = sm + 32256;         // total 36864 bf16 = 73728 B

    const int tid = threadIdx.x, wid = tid >> 5, lane = tid & 31;
    const int qt = 15 - blockIdx.x;          // heavy tiles first
    const int h = blockIdx.y, b = blockIdx.z;
    const int m0 = qt * 128;
    const size_t base = ((size_t)(b * Hh + h)) * Tt * Dd;

    // stage Q hi/lo
    #pragma unroll
    for (int i = 0; i < 8; i++) {
        int id = tid + i * 128;
        int r = id >> 3, c = id & 7;
        size_t src = base + (size_t)(m0 + r) * Dd + c * 8;
        *(float4*)&Qh[r * 72 + c * 8] = *(const float4*)&g_qh[src];
        *(float4*)&Ql[r * 72 + c * 8] = *(const float4*)&g_ql[src];
    }

    const int wm = wid * 32;
    const int lr = lane & 15, lc = (lane >> 4) * 8;
    const int g = lane >> 2, tg = lane & 3;
    const uint32_t QhB = smem_u32(Qh), QlB = smem_u32(Ql);
    const uint32_t KhB = smem_u32(Kh), KlB = smem_u32(Kl);
    const uint32_t VhB = smem_u32(Vh), VlB = smem_u32(Vl);

    float o[2][8][4];
    #pragma unroll
    for (int mt = 0; mt < 2; mt++)
        #pragma unroll
        for (int nt = 0; nt < 8; nt++)
            #pragma unroll
            for (int c = 0; c < 4; c++) o[mt][nt][c] = 0.f;
    float mrow[4] = {-1e30f, -1e30f, -1e30f, -1e30f};
    float lrow[4] = {0.f, 0.f, 0.f, 0.f};

    const int ntiles = 2 * qt + 2;
    for (int kt = 0; kt < ntiles; kt++) {
        // stage K/V tile hi/lo
        #pragma unroll
        for (int i = 0; i < 4; i++) {
            int id = tid + i * 128;
            int r = id >> 3, c = id & 7;
            size_t src = base + (size_t)(kt * 64 + r) * Dd + c * 8;
            *(float4*)&Kh[r * 72 + c * 8] = *(const float4*)&g_kh[src];
            *(float4*)&Kl[r * 72 + c * 8] = *(const float4*)&g_kl[src];
            *(float4*)&Vh[r * 72 + c * 8] = *(const float4*)&g_vh[src];
            *(float4*)&Vl[r * 72 + c * 8] = *(const float4*)&g_vl[src];
        }
        __syncthreads();

        // S = Q K^T (3-term)
        float s[2][8][4];
        #pragma unroll
        for (int mt = 0; mt < 2; mt++)
            #pragma unroll
            for (int nt = 0; nt < 8; nt++)
                #pragma unroll
                for (int c = 0; c < 4; c++) s[mt][nt][c] = 0.f;

        #pragma unroll
        for (int ks = 0; ks < 4; ks++) {
            uint32_t qh[2][4], ql[2][4];
            #pragma unroll
            for (int mt = 0; mt < 2; mt++) {
                uint32_t off = (uint32_t)((wm + mt * 16 + lr) * 72 + ks * 16 + lc) * 2;
                ldsm_x4(QhB + off, qh[mt][0], qh[mt][1], qh[mt][2], qh[mt][3]);
                ldsm_x4(QlB + off, ql[mt][0], ql[mt][1], ql[mt][2], ql[mt][3]);
            }
            uint32_t kh[8][2], kl[8][2];
            #pragma unroll
            for (int ng = 0; ng < 4; ng++) {
                uint32_t off = (uint32_t)((ng * 16 + lr) * 72 + ks * 16 + lc) * 2;
                uint32_t r0, r1, r2, r3;
                ldsm_x4(KhB + off, r0, r1, r2, r3);
                kh[ng*2+0][0] = r0; kh[ng*2+0][1] = r2;
                kh[ng*2+1][0] = r1; kh[ng*2+1][1] = r3;
                ldsm_x4(KlB + off, r0, r1, r2, r3);
                kl[ng*2+0][0] = r0; kl[ng*2+0][1] = r2;
                kl[ng*2+1][0] = r1; kl[ng*2+1][1] = r3;
            }
            #pragma unroll
            for (int mt = 0; mt < 2; mt++)
                #pragma unroll
                for (int nt = 0; nt < 8; nt++) {
                    mma_bf16(s[mt][nt], qh[mt], kh[nt]);
                    mma_bf16(s[mt][nt], ql[mt], kh[nt]);
                    mma_bf16(s[mt][nt], qh[mt], kl[nt]);
                }
        }

        // causal mask (only diagonal 128x128 region)
        if (kt >= 2 * qt) {
            #pragma unroll
            for (int mt = 0; mt < 2; mt++)
                #pragma unroll
                for (int nt = 0; nt < 8; nt++)
                    #pragma unroll
                    for (int c = 0; c < 4; c++) {
                        int row = m0 + wm + mt * 16 + (c >> 1) * 8 + g;
                        int kg  = kt * 64 + nt * 8 + tg * 2 + (c & 1);
                        if (kg > row) s[mt][nt][c] = -1e30f;
                    }
        }

        // online softmax (row in shfl quad)
        #pragma unroll
        for (int mt = 0; mt < 2; mt++)
            #pragma unroll
            for (int half = 0; half < 2; half++) {
                const int slot = mt * 2 + half;
                float mx = -1e30f;
                #pragma unroll
                for (int nt = 0; nt < 8; nt++)
                    mx = fmaxf(mx, fmaxf(s[mt][nt][half*2], s[mt][nt][half*2+1]));
                mx = fmaxf(mx, __shfl_xor_sync(0xffffffffu, mx, 1));
                mx = fmaxf(mx, __shfl_xor_sync(0xffffffffu, mx, 2));
                float Mn = fmaxf(mrow[slot], mx);
                float f = __expf(mrow[slot] - Mn);
                mrow[slot] = Mn;
                lrow[slot] *= f;
                float ps = 0.f;
                #pragma unroll
                for (int nt = 0; nt < 8; nt++) {
                    float p0 = __expf(s[mt][nt][half*2+0] - Mn);
                    float p1 = __expf(s[mt][nt][half*2+1] - Mn);
                    s[mt][nt][half*2+0] = p0;
                    s[mt][nt][half*2+1] = p1;
                    ps += p0 + p1;
                    o[mt][nt][half*2+0] *= f;
                    o[mt][nt][half*2+1] *= f;
                }
                ps += __shfl_xor_sync(0xffffffffu, ps, 1);
                ps += __shfl_xor_sync(0xffffffffu, ps, 2);
                lrow[slot] += ps;
            }

        // PV (3-term): P frags from S accum (layout match), V via trans ldsm
        #pragma unroll
        for (int ksp = 0; ksp < 4; ksp++) {
            uint32_t ph[2][4], pl[2][4];
            #pragma unroll
            for (int mt = 0; mt < 2; mt++) {
                ph[mt][0] = pack_hilo(s[mt][2*ksp+0][0], s[mt][2*ksp+0][1], pl[mt][0]);
                ph[mt][1] = pack_hilo(s[mt][2*ksp+0][2], s[mt][2*ksp+0][3], pl[mt][1]);
                ph[mt][2] = pack_hilo(s[mt][2*ksp+1][0], s[mt][2*ksp+1][1], pl[mt][2]);
                ph[mt][3] = pack_hilo(s[mt][2*ksp+1][2], s[mt][2*ksp+1][3], pl[mt][3]);
            }
            uint32_t vh[8][2], vl[8][2];
            #pragma unroll
            for (int ng = 0; ng < 4; ng++) {
                uint32_t off = (uint32_t)((ksp * 16 + lr) * 72 + ng * 16 + lc) * 2;
                uint32_t r0, r1, r2, r3;
                ldsm_x4_t(VhB + off, r0, r1, r2, r3);
                vh[ng*2+0][0] = r0; vh[ng*2+0][1] = r1;
                vh[ng*2+1][0] = r2; vh[ng*2+1][1] = r3;
                ldsm_x4_t(VlB + off, r0, r1, r2, r3);
                vl[ng*2+0][0] = r0; vl[ng*2+0][1] = r1;
                vl[ng*2+1][0] = r2; vl[ng*2+1][1] = r3;
            }
            #pragma unroll
            for (int mt = 0; mt < 2; mt++)
                #pragma unroll
                for (int nt = 0; nt < 8; nt++) {
                    mma_bf16(o[mt][nt], ph[mt], vh[nt]);
                    mma_bf16(o[mt][nt], pl[mt], vh[nt]);
                    mma_bf16(o[mt][nt], ph[mt], vl[nt]);
                }
        }
        __syncthreads();
    }

    // epilogue: normalize, write ctx fp32 [b, t, h*64 + d]
    #pragma unroll
    for (int mt = 0; mt < 2; mt++)
        #pragma unroll
        for (int half = 0; half < 2; half++) {
            const float inv = 1.f / lrow[mt * 2 + half];
            int row = m0 + wm + mt * 16 + half * 8 + g;
            float* dst = g_ctx + ((size_t)(b * Tt + row)) * Cc + h * Dd;
            #pragma unroll
            for (int nt = 0; nt < 8; nt++) {
                float2 v;
                v.x = o[mt][nt][half*2+0] * inv;
                v.y = o[mt][nt][half*2+1] * inv;
                *(float2*)(dst + nt * 8 + tg * 2) = v;
            }
        }
}

// ---------------------------------------------------------------------------
extern "C" void kernel_launch(void* const* d_in, const int* in_sizes, int n_in,
                              void* d_out, int out_size)
{
    const float* x     = (const float*)d_in[0];
    const float* w_qkv = (const float*)d_in[1];
    const float* b_qkv = (const float*)d_in[2];
    const float* w_out = (const float*)d_in[3];
    const float* b_out = (const float*)d_in[4];
    float* out = (float*)d_out;

    constexpr int ATTN_SMEM = 36864 * 2;   // 73728 B
    cudaFuncSetAttribute(attn_mma_kernel,
                         cudaFuncAttributeMaxDynamicSharedMemorySize, ATTN_SMEM);

    // 0) weight transpose + split
    {
        dim3 blk(32, 8);
        conv_w_kernel<0><<<dim3(3072 / 32, 1024 / 32), blk>>>(w_qkv);
        conv_w_kernel<1><<<dim3(1024 / 32, 1024 / 32), blk>>>(w_out);
    }
    // 1) QKV projection -> q/k/v bf16 hi/lo (q pre-scaled)
    tgemm_kernel<3072, 0><<<dim3(3072 / 128, NTOK / 128), 256>>>(x, b_qkv, nullptr);
    // 2) flash attention (HMMA) -> g_ctx
    attn_mma_kernel<<<dim3(16, Hh, Bb), 128, ATTN_SMEM>>>();
    // 3) output projection -> out
    tgemm_kernel<1024, 1><<<dim3(1024 / 128, NTOK / 128), 256>>>(nullptr, b_out, out);
}

// round 5
// speedup vs baseline: 4.1309x; 1.0546x over previous
#include <cuda_runtime.h>
#include <cuda_bf16.h>
#include <cstdint>

#define Bb 4
#define Tt 2048
#define Cc 1024
#define Hh 16
#define Dd 64
#define NTOK (Bb*Tt)   // 8192

// ---------------------------------------------------------------------------
// Scratch (__device__ globals: allocation-free rule)
// ---------------------------------------------------------------------------
__device__ __nv_bfloat16 g_xh[(size_t)NTOK*Cc],  g_xl[(size_t)NTOK*Cc];
__device__ __nv_bfloat16 g_ctxh[(size_t)NTOK*Cc], g_ctxl[(size_t)NTOK*Cc];
__device__ __nv_bfloat16 g_qh[Bb*Hh*Tt*Dd], g_ql[Bb*Hh*Tt*Dd];
__device__ __nv_bfloat16 g_kh[Bb*Hh*Tt*Dd], g_kl[Bb*Hh*Tt*Dd];
__device__ __nv_bfloat16 g_vh[Bb*Hh*Tt*Dd], g_vl[Bb*Hh*Tt*Dd];
__device__ __nv_bfloat16 g_wqkv_hi[3072*1024];
__device__ __nv_bfloat16 g_wqkv_lo[3072*1024];
__device__ __nv_bfloat16 g_wout_hi[1024*1024];
__device__ __nv_bfloat16 g_wout_lo[1024*1024];

// ---------------------------------------------------------------------------
// helpers
// ---------------------------------------------------------------------------
__device__ __forceinline__ uint32_t smem_u32(const void* p) {
    uint32_t a;
    asm("{ .reg .u64 t; cvta.to.shared.u64 t, %1; cvt.u32.u64 %0, t; }"
        : "=r"(a) : "l"(p));
    return a;
}
__device__ __forceinline__ void ldsm_x4(uint32_t addr, uint32_t& r0, uint32_t& r1,
                                        uint32_t& r2, uint32_t& r3) {
    asm volatile("ldmatrix.sync.aligned.m8n8.x4.shared.b16 {%0,%1,%2,%3}, [%4];"
                 : "=r"(r0), "=r"(r1), "=r"(r2), "=r"(r3) : "r"(addr));
}
__device__ __forceinline__ void ldsm_x4_t(uint32_t addr, uint32_t& r0, uint32_t& r1,
                                          uint32_t& r2, uint32_t& r3) {
    asm volatile("ldmatrix.sync.aligned.m8n8.x4.trans.shared.b16 {%0,%1,%2,%3}, [%4];"
                 : "=r"(r0), "=r"(r1), "=r"(r2), "=r"(r3) : "r"(addr));
}
__device__ __forceinline__ void mma_bf16(float* d, const uint32_t* a, const uint32_t* b) {
    asm volatile(
        "mma.sync.aligned.m16n8k16.row.col.f32.bf16.bf16.f32 "
        "{%0,%1,%2,%3}, {%4,%5,%6,%7}, {%8,%9}, {%0,%1,%2,%3};"
        : "+f"(d[0]), "+f"(d[1]), "+f"(d[2]), "+f"(d[3])
        : "r"(a[0]), "r"(a[1]), "r"(a[2]), "r"(a[3]), "r"(b[0]), "r"(b[1]));
}
__device__ __forceinline__ uint32_t pack_hilo(float x, float y, uint32_t& lo) {
    __nv_bfloat16 hx = __float2bfloat16_rn(x), hy = __float2bfloat16_rn(y);
    __nv_bfloat162 h; h.x = hx; h.y = hy;
    __nv_bfloat162 l;
    l.x = __float2bfloat16_rn(x - __bfloat162float(hx));
    l.y = __float2bfloat16_rn(y - __bfloat162float(hy));
    lo = *(uint32_t*)&l;
    return *(uint32_t*)&h;
}
__device__ __forceinline__ void cpa16(uint32_t dst, const void* src) {
    asm volatile("cp.async.ca.shared.global [%0], [%1], 16;" :: "r"(dst), "l"(src));
}
#define CP_COMMIT() asm volatile("cp.async.commit_group;" ::: "memory")
#define CP_WAIT(n)  asm volatile("cp.async.wait_group %0;" :: "n"(n) : "memory")

// ---------------------------------------------------------------------------
// x fp32 -> bf16 hi/lo (elementwise)
// ---------------------------------------------------------------------------
__global__ __launch_bounds__(256) void conv_x_kernel(const float* __restrict__ x)
{
    size_t i = ((size_t)blockIdx.x * 256 + threadIdx.x) * 4;
    float4 v = *(const float4*)(x + i);
    uint32_t l01, l23;
    uint32_t h01 = pack_hilo(v.x, v.y, l01);
    uint32_t h23 = pack_hilo(v.z, v.w, l23);
    uint2 uh; uh.x = h01; uh.y = h23;
    uint2 ul; ul.x = l01; ul.y = l23;
    *(uint2*)(g_xh + i) = uh;
    *(uint2*)(g_xl + i) = ul;
}

// ---------------------------------------------------------------------------
// Weight transpose + bf16 hi/lo split: w[1024][N] -> Wt_hi/lo[N][1024]
// ---------------------------------------------------------------------------
template<int MODE>
__global__ __launch_bounds__(256) void conv_w_kernel(const float* __restrict__ w)
{
    constexpr int N = (MODE == 0) ? 3072 : 1024;
    __nv_bfloat16* th = (MODE == 0) ? g_wqkv_hi : g_wout_hi;
    __nv_bfloat16* tl = (MODE == 0) ? g_wqkv_lo : g_wout_lo;
    __shared__ float tile[32][33];
    const int n0 = blockIdx.x * 32, k0 = blockIdx.y * 32;
    const int tx = threadIdx.x, ty = threadIdx.y;
    #pragma unroll
    for (int i = 0; i < 4; i++) {
        int k = ty + i * 8;
        tile[k][tx] = w[(size_t)(k0 + k) * N + n0 + tx];
    }
    __syncthreads();
    #pragma unroll
    for (int i = 0; i < 4; i++) {
        int r = ty + i * 8;
        float v = tile[tx][r];
        __nv_bfloat16 h = __float2bfloat16_rn(v);
        float l = v - __bfloat162float(h);
        size_t o = (size_t)(n0 + r) * 1024 + k0 + tx;
        th[o] = h;
        tl[o] = __float2bfloat16_rn(l);
    }
}

// ---------------------------------------------------------------------------
// HMMA GEMM, split-bf16 3-term, cp.async double-buffered.
// A hi/lo bf16 [M][1024]; B hi/lo bf16 [N][1024].
// CTA 128x128, 8 warps (2Mx4N), BK=32. smem row stride 40 bf16.
// MODE 0: scatter to q/k/v hi/lo (q pre-scaled). MODE 1: dense fp32 out.
// ---------------------------------------------------------------------------
template<int N, int MODE>
__global__ __launch_bounds__(256, 2) void tgemm_kernel(
    const float* __restrict__ bias, float* __restrict__ Cout)
{
    extern __shared__ __nv_bfloat16 sm[];
    constexpr int LDS = 40;
    constexpr uint32_t T_AH = 0, T_AL = 128*LDS, T_BH = 2*128*LDS, T_BL = 3*128*LDS;
    constexpr uint32_t STAGE = 4*128*LDS;          // bf16 elems per stage

    const __nv_bfloat16* Ah = (MODE == 0) ? g_xh : g_ctxh;
    const __nv_bfloat16* Al = (MODE == 0) ? g_xl : g_ctxl;
    const __nv_bfloat16* Wh = (MODE == 0) ? g_wqkv_hi : g_wout_hi;
    const __nv_bfloat16* Wl = (MODE == 0) ? g_wqkv_lo : g_wout_lo;

    const int tid  = threadIdx.x;
    const int wid  = tid >> 5, lane = tid & 31;
    const int wm   = (wid >> 2) * 64;
    const int wn   = (wid & 3) * 32;
    const int lr   = lane & 15, lc = (lane >> 4) * 8;
    const int n0   = blockIdx.x * 128, m0 = blockIdx.y * 128;
    const uint32_t smB = smem_u32(sm);

    // cp.async per-thread addressing: 2 iters, each loads one 16B chunk/array
    const int ldr = tid >> 2, ldc = tid & 3;       // row, 16B-chunk

    float acc[4][4][4];
    #pragma unroll
    for (int i = 0; i < 4; i++)
        #pragma unroll
        for (int j = 0; j < 4; j++)
            #pragma unroll
            for (int c = 0; c < 4; c++) acc[i][j][c] = 0.f;

    auto load_chunk = [&](int ch, int stg) {
        const int k0 = ch * 32;
        const uint32_t sb = smB + stg * STAGE * 2;
        #pragma unroll
        for (int i = 0; i < 2; i++) {
            int r = ldr + i * 64;
            uint32_t doff = (uint32_t)(r * LDS + ldc * 8) * 2;
            size_t ga = (size_t)(m0 + r) * 1024 + k0 + ldc * 8;
            size_t gb = (size_t)(n0 + r) * 1024 + k0 + ldc * 8;
            cpa16(sb + T_AH*2 + doff, Ah + ga);
            cpa16(sb + T_AL*2 + doff, Al + ga);
            cpa16(sb + T_BH*2 + doff, Wh + gb);
            cpa16(sb + T_BL*2 + doff, Wl + gb);
        }
        CP_COMMIT();
    };

    load_chunk(0, 0);

    for (int ch = 0; ch < 32; ch++) {
        if (ch + 1 < 32) load_chunk(ch + 1, (ch + 1) & 1);
        if (ch + 1 < 32) { CP_WAIT(1); } else { CP_WAIT(0); }
        __syncthreads();

        const uint32_t sb = smB + (ch & 1) * STAGE * 2;
        const uint32_t aHB = sb + T_AH*2, aLB = sb + T_AL*2;
        const uint32_t bHB = sb + T_BH*2, bLB = sb + T_BL*2;

        #pragma unroll
        for (int half = 0; half < 2; half++) {
            const int kk = half * 16;
            uint32_t aH[4][4], aL[4][4], bH[4][2], bL[4][2];
            #pragma unroll
            for (int mt = 0; mt < 4; mt++) {
                uint32_t off = (uint32_t)((wm + mt * 16 + lr) * LDS + kk + lc) * 2;
                ldsm_x4(aHB + off, aH[mt][0], aH[mt][1], aH[mt][2], aH[mt][3]);
                ldsm_x4(aLB + off, aL[mt][0], aL[mt][1], aL[mt][2], aL[mt][3]);
            }
            #pragma unroll
            for (int np = 0; np < 2; np++) {
                uint32_t off = (uint32_t)((wn + np * 16 + lr) * LDS + kk + lc) * 2;
                uint32_t r0, r1, r2, r3;
                ldsm_x4(bHB + off, r0, r1, r2, r3);
                bH[np*2+0][0] = r0; bH[np*2+0][1] = r2;
                bH[np*2+1][0] = r1; bH[np*2+1][1] = r3;
                ldsm_x4(bLB + off, r0, r1, r2, r3);
                bL[np*2+0][0] = r0; bL[np*2+0][1] = r2;
                bL[np*2+1][0] = r1; bL[np*2+1][1] = r3;
            }
            #pragma unroll
            for (int mt = 0; mt < 4; mt++)
                #pragma unroll
                for (int nt = 0; nt < 4; nt++) {
                    mma_bf16(acc[mt][nt], aH[mt], bH[nt]);
                    mma_bf16(acc[mt][nt], aL[mt], bH[nt]);
                    mma_bf16(acc[mt][nt], aH[mt], bL[nt]);
                }
        }
        __syncthreads();
    }

    const int g = lane >> 2, tg = lane & 3;
    #pragma unroll
    for (int mt = 0; mt < 4; mt++)
        #pragma unroll
        for (int nt = 0; nt < 4; nt++) {
            int n = n0 + wn + nt * 8 + tg * 2;
            float bx = __ldg(bias + n), by = __ldg(bias + n + 1);
            #pragma unroll
            for (int hrow = 0; hrow < 2; hrow++) {
                int m = m0 + wm + mt * 16 + g + hrow * 8;
                float vx = acc[mt][nt][hrow * 2 + 0] + bx;
                float vy = acc[mt][nt][hrow * 2 + 1] + by;
                if (MODE == 0) {
                    int s   = n >> 10;
                    int rem = n & 1023;
                    int hh  = rem >> 6, dd = rem & 63;
                    int bi  = m >> 11, t = m & 2047;
                    if (s == 0) { vx *= 0.125f; vy *= 0.125f; }  // q pre-scale
                    uint32_t lo;
                    uint32_t hi = pack_hilo(vx, vy, lo);
                    __nv_bfloat16* dh = (s == 0) ? g_qh : (s == 1) ? g_kh : g_vh;
                    __nv_bfloat16* dl = (s == 0) ? g_ql : (s == 1) ? g_kl : g_vl;
                    size_t off = (((size_t)(bi * Hh + hh)) * Tt + t) * Dd + dd;
                    *(uint32_t*)(dh + off) = hi;
                    *(uint32_t*)(dl + off) = lo;
                } else {
                    float2 o; o.x = vx; o.y = vy;
                    *(float2*)(Cout + (size_t)m * N + n) = o;
                }
            }
        }
}

// ---------------------------------------------------------------------------
// Flash attention via mma.sync (unchanged mainloop from R4).
// Epilogue now writes ctx as bf16 hi/lo.
// ---------------------------------------------------------------------------
__global__ __launch_bounds__(128, 2) void attn_mma_kernel()
{
    extern __shared__ __nv_bfloat16 sm[];
    __nv_bfloat16* Qh = sm;                 // 128*72
    __nv_bfloat16* Ql = sm + 9216;
    __nv_bfloat16* Kh = sm + 18432;         // 64*72
    __nv_bfloat16* Kl = sm + 23040;
    __nv_bfloat16* Vh = sm + 27648;
    __nv_bfloat16* Vl = sm + 32256;

    const int tid = threadIdx.x, wid = tid >> 5, lane = tid & 31;
    const int qt = 15 - blockIdx.x;
    const int h = blockIdx.y, b = blockIdx.z;
    const int m0 = qt * 128;
    const size_t base = ((size_t)(b * Hh + h)) * Tt * Dd;

    #pragma unroll
    for (int i = 0; i < 8; i++) {
        int id = tid + i * 128;
        int r = id >> 3, c = id & 7;
        size_t src = base + (size_t)(m0 + r) * Dd + c * 8;
        *(float4*)&Qh[r * 72 + c * 8] = *(const float4*)&g_qh[src];
        *(float4*)&Ql[r * 72 + c * 8] = *(const float4*)&g_ql[src];
    }

    const int wm = wid * 32;
    const int lr = lane & 15, lc = (lane >> 4) * 8;
    const int g = lane >> 2, tg = lane & 3;
    const uint32_t QhB = smem_u32(Qh), QlB = smem_u32(Ql);
    const uint32_t KhB = smem_u32(Kh), KlB = smem_u32(Kl);
    const uint32_t VhB = smem_u32(Vh), VlB = smem_u32(Vl);

    float o[2][8][4];
    #pragma unroll
    for (int mt = 0; mt < 2; mt++)
        #pragma unroll
        for (int nt = 0; nt < 8; nt++)
            #pragma unroll
            for (int c = 0; c < 4; c++) o[mt][nt][c] = 0.f;
    float mrow[4] = {-1e30f, -1e30f, -1e30f, -1e30f};
    float lrow[4] = {0.f, 0.f, 0.f, 0.f};

    const int ntiles = 2 * qt + 2;
    for (int kt = 0; kt < ntiles; kt++) {
        #pragma unroll
        for (int i = 0; i < 4; i++) {
            int id = tid + i * 128;
            int r = id >> 3, c = id & 7;
            size_t src = base + (size_t)(kt * 64 + r) * Dd + c * 8;
            *(float4*)&Kh[r * 72 + c * 8] = *(const float4*)&g_kh[src];
            *(float4*)&Kl[r * 72 + c * 8] = *(const float4*)&g_kl[src];
            *(float4*)&Vh[r * 72 + c * 8] = *(const float4*)&g_vh[src];
            *(float4*)&Vl[r * 72 + c * 8] = *(const float4*)&g_vl[src];
        }
        __syncthreads();

        float s[2][8][4];
        #pragma unroll
        for (int mt = 0; mt < 2; mt++)
            #pragma unroll
            for (int nt = 0; nt < 8; nt++)
                #pragma unroll
                for (int c = 0; c < 4; c++) s[mt][nt][c] = 0.f;

        #pragma unroll
        for (int ks = 0; ks < 4; ks++) {
            uint32_t qh[2][4], ql[2][4];
            #pragma unroll
            for (int mt = 0; mt < 2; mt++) {
                uint32_t off = (uint32_t)((wm + mt * 16 + lr) * 72 + ks * 16 + lc) * 2;
                ldsm_x4(QhB + off, qh[mt][0], qh[mt][1], qh[mt][2], qh[mt][3]);
                ldsm_x4(QlB + off, ql[mt][0], ql[mt][1], ql[mt][2], ql[mt][3]);
            }
            uint32_t kh[8][2], kl[8][2];
            #pragma unroll
            for (int ng = 0; ng < 4; ng++) {
                uint32_t off = (uint32_t)((ng * 16 + lr) * 72 + ks * 16 + lc) * 2;
                uint32_t r0, r1, r2, r3;
                ldsm_x4(KhB + off, r0, r1, r2, r3);
                kh[ng*2+0][0] = r0; kh[ng*2+0][1] = r2;
                kh[ng*2+1][0] = r1; kh[ng*2+1][1] = r3;
                ldsm_x4(KlB + off, r0, r1, r2, r3);
                kl[ng*2+0][0] = r0; kl[ng*2+0][1] = r2;
                kl[ng*2+1][0] = r1; kl[ng*2+1][1] = r3;
            }
            #pragma unroll
            for (int mt = 0; mt < 2; mt++)
                #pragma unroll
                for (int nt = 0; nt < 8; nt++) {
                    mma_bf16(s[mt][nt], qh[mt], kh[nt]);
                    mma_bf16(s[mt][nt], ql[mt], kh[nt]);
                    mma_bf16(s[mt][nt], qh[mt], kl[nt]);
                }
        }

        if (kt >= 2 * qt) {
            #pragma unroll
            for (int mt = 0; mt < 2; mt++)
                #pragma unroll
                for (int nt = 0; nt < 8; nt++)
                    #pragma unroll
                    for (int c = 0; c < 4; c++) {
                        int row = m0 + wm + mt * 16 + (c >> 1) * 8 + g;
                        int kg  = kt * 64 + nt * 8 + tg * 2 + (c & 1);
                        if (kg > row) s[mt][nt][c] = -1e30f;
                    }
        }

        #pragma unroll
        for (int mt = 0; mt < 2; mt++)
            #pragma unroll
            for (int half = 0; half < 2; half++) {
                const int slot = mt * 2 + half;
                float mx = -1e30f;
                #pragma unroll
                for (int nt = 0; nt < 8; nt++)
                    mx = fmaxf(mx, fmaxf(s[mt][nt][half*2], s[mt][nt][half*2+1]));
                mx = fmaxf(mx, __shfl_xor_sync(0xffffffffu, mx, 1));
                mx = fmaxf(mx, __shfl_xor_sync(0xffffffffu, mx, 2));
                float Mn = fmaxf(mrow[slot], mx);
                float f = __expf(mrow[slot] - Mn);
                mrow[slot] = Mn;
                lrow[slot] *= f;
                float ps = 0.f;
                #pragma unroll
                for (int nt = 0; nt < 8; nt++) {
                    float p0 = __expf(s[mt][nt][half*2+0] - Mn);
                    float p1 = __expf(s[mt][nt][half*2+1] - Mn);
                    s[mt][nt][half*2+0] = p0;
                    s[mt][nt][half*2+1] = p1;
                    ps += p0 + p1;
                    o[mt][nt][half*2+0] *= f;
                    o[mt][nt][half*2+1] *= f;
                }
                ps += __shfl_xor_sync(0xffffffffu, ps, 1);
                ps += __shfl_xor_sync(0xffffffffu, ps, 2);
                lrow[slot] += ps;
            }

        #pragma unroll
        for (int ksp = 0; ksp < 4; ksp++) {
            uint32_t ph[2][4], pl[2][4];
            #pragma unroll
            for (int mt = 0; mt < 2; mt++) {
                ph[mt][0] = pack_hilo(s[mt][2*ksp+0][0], s[mt][2*ksp+0][1], pl[mt][0]);
                ph[mt][1] = pack_hilo(s[mt][2*ksp+0][2], s[mt][2*ksp+0][3], pl[mt][1]);
                ph[mt][2] = pack_hilo(s[mt][2*ksp+1][0], s[mt][2*ksp+1][1], pl[mt][2]);
                ph[mt][3] = pack_hilo(s[mt][2*ksp+1][2], s[mt][2*ksp+1][3], pl[mt][3]);
            }
            uint32_t vh[8][2], vl[8][2];
            #pragma unroll
            for (int ng = 0; ng < 4; ng++) {
                uint32_t off = (uint32_t)((ksp * 16 + lr) * 72 + ng * 16 + lc) * 2;
                uint32_t r0, r1, r2, r3;
                ldsm_x4_t(VhB + off, r0, r1, r2, r3);
                vh[ng*2+0][0] = r0; vh[ng*2+0][1] = r1;
                vh[ng*2+1][0] = r2; vh[ng*2+1][1] = r3;
                ldsm_x4_t(VlB + off, r0, r1, r2, r3);
                vl[ng*2+0][0] = r0; vl[ng*2+0][1] = r1;
                vl[ng*2+1][0] = r2; vl[ng*2+1][1] = r3;
            }
            #pragma unroll
            for (int mt = 0; mt < 2; mt++)
                #pragma unroll
                for (int nt = 0; nt < 8; nt++) {
                    mma_bf16(o[mt][nt], ph[mt], vh[nt]);
                    mma_bf16(o[mt][nt], pl[mt], vh[nt]);
                    mma_bf16(o[mt][nt], ph[mt], vl[nt]);
                }
        }
        __syncthreads();
    }

    // epilogue: normalize, write ctx bf16 hi/lo [b, t, h*64 + d]
    #pragma unroll
    for (int mt = 0; mt < 2; mt++)
        #pragma unroll
        for (int half = 0; half < 2; half++) {
            const float inv = 1.f / lrow[mt * 2 + half];
            int row = m0 + wm + mt * 16 + half * 8 + g;
            size_t doff = ((size_t)(b * Tt + row)) * Cc + h * Dd;
            #pragma unroll
            for (int nt = 0; nt < 8; nt++) {
                uint32_t lo;
                uint32_t hi = pack_hilo(o[mt][nt][half*2+0] * inv,
                                        o[mt][nt][half*2+1] * inv, lo);
                *(uint32_t*)(g_ctxh + doff + nt * 8 + tg * 2) = hi;
                *(uint32_t*)(g_ctxl + doff + nt * 8 + tg * 2) = lo;
            }
        }
}

// ---------------------------------------------------------------------------
extern "C" void kernel_launch(void* const* d_in, const int* in_sizes, int n_in,
                              void* d_out, int out_size)
{
    const float* x     = (const float*)d_in[0];
    const float* w_qkv = (const float*)d_in[1];
    const float* b_qkv = (const float*)d_in[2];
    const float* w_out = (const float*)d_in[3];
    const float* b_out = (const float*)d_in[4];
    float* out = (float*)d_out;

    constexpr int ATTN_SMEM = 36864 * 2;                 // 73728 B
    constexpr int TG_SMEM   = 2 * 4 * 128 * 40 * 2;      // 81920 B
    cudaFuncSetAttribute(attn_mma_kernel,
                         cudaFuncAttributeMaxDynamicSharedMemorySize, ATTN_SMEM);
    cudaFuncSetAttribute(tgemm_kernel<3072, 0>,
                         cudaFuncAttributeMaxDynamicSharedMemorySize, TG_SMEM);
    cudaFuncSetAttribute(tgemm_kernel<1024, 1>,
                         cudaFuncAttributeMaxDynamicSharedMemorySize, TG_SMEM);

    // 0) conversions
    conv_x_kernel<<<(size_t)NTOK * Cc / (256 * 4), 256>>>(x);
    {
        dim3 blk(32, 8);
        conv_w_kernel<0><<<dim3(3072 / 32, 1024 / 32), blk>>>(w_qkv);
        conv_w_kernel<1><<<dim3(1024 / 32, 1024 / 32), blk>>>(w_out);
    }
    // 1) QKV projection -> q/k/v bf16 hi/lo
    tgemm_kernel<3072, 0><<<dim3(3072 / 128, NTOK / 128), 256, TG_SMEM>>>(b_qkv, nullptr);
    // 2) flash attention -> ctx bf16 hi/lo
    attn_mma_kernel<<<dim3(16, Hh, Bb), 128, ATTN_SMEM>>>();
    // 3) output projection -> out (fp32)
    tgemm_kernel<1024, 1><<<dim3(1024 / 128, NTOK / 128), 256, TG_SMEM>>>(b_out, out);
}

// round 7
// speedup vs baseline: 10.1355x; 2.4536x over previous
#include <cuda_runtime.h>
#include <cuda_fp16.h>
#include <cstdint>

#define Bb 4
#define Tt 2048
#define Cc 1024
#define Hh 16
#define Dd 64
#define NTOK (Bb*Tt)   // 8192

// ---------------------------------------------------------------------------
// Scratch (__device__ globals)
// ---------------------------------------------------------------------------
__device__ __half g_x16[(size_t)NTOK*Cc];
__device__ __half g_ctx16[(size_t)NTOK*Cc];
__device__ __half g_q16[Bb*Hh*Tt*Dd], g_k16[Bb*Hh*Tt*Dd], g_v16[Bb*Hh*Tt*Dd];
__device__ __half g_wqkv16[3072*1024];
__device__ __half g_wout16[1024*1024];

// ---------------------------------------------------------------------------
// helpers
// ---------------------------------------------------------------------------
__device__ __forceinline__ uint32_t smem_u32(const void* p) {
    uint32_t a;
    asm("{ .reg .u64 t; cvta.to.shared.u64 t, %1; cvt.u32.u64 %0, t; }"
        : "=r"(a) : "l"(p));
    return a;
}
__device__ __forceinline__ void ldsm_x4(uint32_t addr, uint32_t& r0, uint32_t& r1,
                                        uint32_t& r2, uint32_t& r3) {
    asm volatile("ldmatrix.sync.aligned.m8n8.x4.shared.b16 {%0,%1,%2,%3}, [%4];"
                 : "=r"(r0), "=r"(r1), "=r"(r2), "=r"(r3) : "r"(addr));
}
__device__ __forceinline__ void ldsm_x4_t(uint32_t addr, uint32_t& r0, uint32_t& r1,
                                          uint32_t& r2, uint32_t& r3) {
    asm volatile("ldmatrix.sync.aligned.m8n8.x4.trans.shared.b16 {%0,%1,%2,%3}, [%4];"
                 : "=r"(r0), "=r"(r1), "=r"(r2), "=r"(r3) : "r"(addr));
}
__device__ __forceinline__ void mma_f16(float* d, const uint32_t* a, const uint32_t* b) {
    asm volatile(
        "mma.sync.aligned.m16n8k16.row.col.f32.f16.f16.f32 "
        "{%0,%1,%2,%3}, {%4,%5,%6,%7}, {%8,%9}, {%0,%1,%2,%3};"
        : "+f"(d[0]), "+f"(d[1]), "+f"(d[2]), "+f"(d[3])
        : "r"(a[0]), "r"(a[1]), "r"(a[2]), "r"(a[3]), "r"(b[0]), "r"(b[1]));
}
__device__ __forceinline__ uint32_t packh2(float x, float y) {
    __half2 h = __floats2half2_rn(x, y);
    return *(uint32_t*)&h;
}
__device__ __forceinline__ void cpa16(uint32_t dst, const void* src) {
    asm volatile("cp.async.ca.shared.global [%0], [%1], 16;" :: "r"(dst), "l"(src));
}
#define CP_COMMIT() asm volatile("cp.async.commit_group;" ::: "memory")
#define CP_WAIT(n)  asm volatile("cp.async.wait_group %0;" :: "n"(n) : "memory")

// ---------------------------------------------------------------------------
// x fp32 -> fp16
// ---------------------------------------------------------------------------
__global__ __launch_bounds__(256) void conv_x_kernel(const float* __restrict__ x)
{
    size_t i = ((size_t)blockIdx.x * 256 + threadIdx.x) * 4;
    float4 v = *(const float4*)(x + i);
    uint2 u;
    u.x = packh2(v.x, v.y);
    u.y = packh2(v.z, v.w);
    *(uint2*)(g_x16 + i) = u;
}

// ---------------------------------------------------------------------------
// Weight transpose + fp16: w[1024][N] -> Wt[N][1024]
// ---------------------------------------------------------------------------
template<int MODE>
__global__ __launch_bounds__(256) void conv_w_kernel(const float* __restrict__ w)
{
    constexpr int N = (MODE == 0) ? 3072 : 1024;
    __half* th = (MODE == 0) ? g_wqkv16 : g_wout16;
    __shared__ float tile[32][33];
    const int n0 = blockIdx.x * 32, k0 = blockIdx.y * 32;
    const int tx = threadIdx.x, ty = threadIdx.y;
    #pragma unroll
    for (int i = 0; i < 4; i++) {
        int k = ty + i * 8;
        tile[k][tx] = w[(size_t)(k0 + k) * N + n0 + tx];
    }
    __syncthreads();
    #pragma unroll
    for (int i = 0; i < 4; i++) {
        int r = ty + i * 8;
        th[(size_t)(n0 + r) * 1024 + k0 + tx] = __float2half_rn(tile[tx][r]);
    }
}

// ---------------------------------------------------------------------------
// fp16 HMMA GEMM, cp.async double-buffered.
// A fp16 [M][1024]; B fp16 [N][1024] (pre-transposed).
// CTA 128x128, 8 warps (2Mx4N), BK=32, smem row stride 40 halves.
// MODE 0: scatter to q/k/v fp16 (q pre-scaled). MODE 1: dense fp32 out.
// ---------------------------------------------------------------------------
template<int N, int MODE>
__global__ __launch_bounds__(256, 2) void tgemm_kernel(
    const float* __restrict__ bias, float* __restrict__ Cout)
{
    extern __shared__ __half sm[];
    constexpr int LDS = 40;
    constexpr uint32_t T_A = 0, T_B = 128*LDS;
    constexpr uint32_t STAGE = 2*128*LDS;           // halves per stage

    const __half* A = (MODE == 0) ? g_x16 : g_ctx16;
    const __half* W = (MODE == 0) ? g_wqkv16 : g_wout16;

    const int tid  = threadIdx.x;
    const int wid  = tid >> 5, lane = tid & 31;
    const int wm   = (wid >> 2) * 64;
    const int wn   = (wid & 3) * 32;
    const int lr   = lane & 15, lc = (lane >> 4) * 8;
    const int n0   = blockIdx.x * 128, m0 = blockIdx.y * 128;
    const uint32_t smB = smem_u32(sm);

    const int ldr = tid >> 2, ldc = tid & 3;

    float acc[4][4][4];
    #pragma unroll
    for (int i = 0; i < 4; i++)
        #pragma unroll
        for (int j = 0; j < 4; j++)
            #pragma unroll
            for (int c = 0; c < 4; c++) acc[i][j][c] = 0.f;

    auto load_chunk = [&](int ch, int stg) {
        const int k0 = ch * 32;
        const uint32_t sb = smB + stg * STAGE * 2;
        #pragma unroll
        for (int i = 0; i < 2; i++) {
            int r = ldr + i * 64;
            uint32_t doff = (uint32_t)(r * LDS + ldc * 8) * 2;
            cpa16(sb + T_A*2 + doff, A + (size_t)(m0 + r) * 1024 + k0 + ldc * 8);
            cpa16(sb + T_B*2 + doff, W + (size_t)(n0 + r) * 1024 + k0 + ldc * 8);
        }
        CP_COMMIT();
    };

    load_chunk(0, 0);

    for (int ch = 0; ch < 32; ch++) {
        if (ch + 1 < 32) load_chunk(ch + 1, (ch + 1) & 1);
        if (ch + 1 < 32) { CP_WAIT(1); } else { CP_WAIT(0); }
        __syncthreads();

        const uint32_t sb = smB + (ch & 1) * STAGE * 2;
        const uint32_t aB = sb + T_A*2, bB = sb + T_B*2;

        #pragma unroll
        for (int half = 0; half < 2; half++) {
            const int kk = half * 16;
            uint32_t a[4][4], b[4][2];
            #pragma unroll
            for (int mt = 0; mt < 4; mt++) {
                uint32_t off = (uint32_t)((wm + mt * 16 + lr) * LDS + kk + lc) * 2;
                ldsm_x4(aB + off, a[mt][0], a[mt][1], a[mt][2], a[mt][3]);
            }
            #pragma unroll
            for (int np = 0; np < 2; np++) {
                uint32_t off = (uint32_t)((wn + np * 16 + lr) * LDS + kk + lc) * 2;
                uint32_t r0, r1, r2, r3;
                ldsm_x4(bB + off, r0, r1, r2, r3);
                b[np*2+0][0] = r0; b[np*2+0][1] = r2;
                b[np*2+1][0] = r1; b[np*2+1][1] = r3;
            }
            #pragma unroll
            for (int mt = 0; mt < 4; mt++)
                #pragma unroll
                for (int nt = 0; nt < 4; nt++)
                    mma_f16(acc[mt][nt], a[mt], b[nt]);
        }
        __syncthreads();
    }

    const int g = lane >> 2, tg = lane & 3;
    #pragma unroll
    for (int mt = 0; mt < 4; mt++)
        #pragma unroll
        for (int nt = 0; nt < 4; nt++) {
            int n = n0 + wn + nt * 8 + tg * 2;
            float bx = __ldg(bias + n), by = __ldg(bias + n + 1);
            #pragma unroll
            for (int hrow = 0; hrow < 2; hrow++) {
                int m = m0 + wm + mt * 16 + g + hrow * 8;
                float vx = acc[mt][nt][hrow * 2 + 0] + bx;
                float vy = acc[mt][nt][hrow * 2 + 1] + by;
                if (MODE == 0) {
                    int s   = n >> 10;
                    int rem = n & 1023;
                    int hh  = rem >> 6, dd = rem & 63;
                    int bi  = m >> 11, t = m & 2047;
                    if (s == 0) { vx *= 0.125f; vy *= 0.125f; }  // q pre-scale
                    __half* dst = (s == 0) ? g_q16 : (s == 1) ? g_k16 : g_v16;
                    size_t off = (((size_t)(bi * Hh + hh)) * Tt + t) * Dd + dd;
                    *(uint32_t*)(dst + off) = packh2(vx, vy);
                } else {
                    float2 o; o.x = vx; o.y = vy;
                    *(float2*)(Cout + (size_t)m * N + n) = o;
                }
            }
        }
}

// ---------------------------------------------------------------------------
// Flash attention, single fp16 mma path.
// CTA: 128 q rows, 4 warps. K/V tiles of 64 keys. smem stride 72 halves.
// ---------------------------------------------------------------------------
__global__ __launch_bounds__(128, 2) void attn_mma_kernel()
{
    extern __shared__ __half sm[];
    __half* Qs = sm;                 // 128*72
    __half* Ks = sm + 9216;          // 64*72
    __half* Vs = sm + 13824;         // 64*72  (total 18432 halves = 36864 B)

    const int tid = threadIdx.x, wid = tid >> 5, lane = tid & 31;
    const int qt = 15 - blockIdx.x;
    const int h = blockIdx.y, b = blockIdx.z;
    const int m0 = qt * 128;
    const size_t base = ((size_t)(b * Hh + h)) * Tt * Dd;

    #pragma unroll
    for (int i = 0; i < 8; i++) {
        int id = tid + i * 128;
        int r = id >> 3, c = id & 7;
        *(float4*)&Qs[r * 72 + c * 8] = *(const float4*)&g_q16[base + (size_t)(m0 + r) * Dd + c * 8];
    }

    const int wm = wid * 32;
    const int lr = lane & 15, lc = (lane >> 4) * 8;
    const int g = lane >> 2, tg = lane & 3;
    const uint32_t QB = smem_u32(Qs), KB = smem_u32(Ks), VB = smem_u32(Vs);

    float o[2][8][4];
    #pragma unroll
    for (int mt = 0; mt < 2; mt++)
        #pragma unroll
        for (int nt = 0; nt < 8; nt++)
            #pragma unroll
            for (int c = 0; c < 4; c++) o[mt][nt][c] = 0.f;
    float mrow[4] = {-1e30f, -1e30f, -1e30f, -1e30f};
    float lrow[4] = {0.f, 0.f, 0.f, 0.f};

    const int ntiles = 2 * qt + 2;
    for (int kt = 0; kt < ntiles; kt++) {
        #pragma unroll
        for (int i = 0; i < 4; i++) {
            int id = tid + i * 128;
            int r = id >> 3, c = id & 7;
            size_t src = base + (size_t)(kt * 64 + r) * Dd + c * 8;
            *(float4*)&Ks[r * 72 + c * 8] = *(const float4*)&g_k16[src];
            *(float4*)&Vs[r * 72 + c * 8] = *(const float4*)&g_v16[src];
        }
        __syncthreads();

        float s[2][8][4];
        #pragma unroll
        for (int mt = 0; mt < 2; mt++)
            #pragma unroll
            for (int nt = 0; nt < 8; nt++)
                #pragma unroll
                for (int c = 0; c < 4; c++) s[mt][nt][c] = 0.f;

        #pragma unroll
        for (int ks = 0; ks < 4; ks++) {
            uint32_t q[2][4];
            #pragma unroll
            for (int mt = 0; mt < 2; mt++) {
                uint32_t off = (uint32_t)((wm + mt * 16 + lr) * 72 + ks * 16 + lc) * 2;
                ldsm_x4(QB + off, q[mt][0], q[mt][1], q[mt][2], q[mt][3]);
            }
            uint32_t k[8][2];
            #pragma unroll
            for (int ng = 0; ng < 4; ng++) {
                uint32_t off = (uint32_t)((ng * 16 + lr) * 72 + ks * 16 + lc) * 2;
                uint32_t r0, r1, r2, r3;
                ldsm_x4(KB + off, r0, r1, r2, r3);
                k[ng*2+0][0] = r0; k[ng*2+0][1] = r2;
                k[ng*2+1][0] = r1; k[ng*2+1][1] = r3;
            }
            #pragma unroll
            for (int mt = 0; mt < 2; mt++)
                #pragma unroll
                for (int nt = 0; nt < 8; nt++)
                    mma_f16(s[mt][nt], q[mt], k[nt]);
        }

        if (kt >= 2 * qt) {
            #pragma unroll
            for (int mt = 0; mt < 2; mt++)
                #pragma unroll
                for (int nt = 0; nt < 8; nt++)
                    #pragma unroll
                    for (int c = 0; c < 4; c++) {
                        int row = m0 + wm + mt * 16 + (c >> 1) * 8 + g;
                        int kg  = kt * 64 + nt * 8 + tg * 2 + (c & 1);
                        if (kg > row) s[mt][nt][c] = -1e30f;
                    }
        }

        #pragma unroll
        for (int mt = 0; mt < 2; mt++)
            #pragma unroll
            for (int half = 0; half < 2; half++) {
                const int slot = mt * 2 + half;
                float mx = -1e30f;
                #pragma unroll
                for (int nt = 0; nt < 8; nt++)
                    mx = fmaxf(mx, fmaxf(s[mt][nt][half*2], s[mt][nt][half*2+1]));
                mx = fmaxf(mx, __shfl_xor_sync(0xffffffffu, mx, 1));
                mx = fmaxf(mx, __shfl_xor_sync(0xffffffffu, mx, 2));
                float Mn = fmaxf(mrow[slot], mx);
                float f = __expf(mrow[slot] - Mn);
                mrow[slot] = Mn;
                lrow[slot] *= f;
                float ps = 0.f;
                #pragma unroll
                for (int nt = 0; nt < 8; nt++) {
                    float p0 = __expf(s[mt][nt][half*2+0] - Mn);
                    float p1 = __expf(s[mt][nt][half*2+1] - Mn);
                    s[mt][nt][half*2+0] = p0;
                    s[mt][nt][half*2+1] = p1;
                    ps += p0 + p1;
                    o[mt][nt][half*2+0] *= f;
                    o[mt][nt][half*2+1] *= f;
                }
                ps += __shfl_xor_sync(0xffffffffu, ps, 1);
                ps += __shfl_xor_sync(0xffffffffu, ps, 2);
                lrow[slot] += ps;
            }

        #pragma unroll
        for (int ksp = 0; ksp < 4; ksp++) {
            uint32_t p[2][4];
            #pragma unroll
            for (int mt = 0; mt < 2; mt++) {
                p[mt][0] = packh2(s[mt][2*ksp+0][0], s[mt][2*ksp+0][1]);
                p[mt][1] = packh2(s[mt][2*ksp+0][2], s[mt][2*ksp+0][3]);
                p[mt][2] = packh2(s[mt][2*ksp+1][0], s[mt][2*ksp+1][1]);
                p[mt][3] = packh2(s[mt][2*ksp+1][2], s[mt][2*ksp+1][3]);
            }
            uint32_t v[8][2];
            #pragma unroll
            for (int ng = 0; ng < 4; ng++) {
                uint32_t off = (uint32_t)((ksp * 16 + lr) * 72 + ng * 16 + lc) * 2;
                uint32_t r0, r1, r2, r3;
                ldsm_x4_t(VB + off, r0, r1, r2, r3);
                v[ng*2+0][0] = r0; v[ng*2+0][1] = r1;
                v[ng*2+1][0] = r2; v[ng*2+1][1] = r3;
            }
            #pragma unroll
            for (int mt = 0; mt < 2; mt++)
                #pragma unroll
                for (int nt = 0; nt < 8; nt++)
                    mma_f16(o[mt][nt], p[mt], v[nt]);
        }
        __syncthreads();
    }

    // epilogue: normalize, write ctx fp16 [b, t, h*64 + d]
    #pragma unroll
    for (int mt = 0; mt < 2; mt++)
        #pragma unroll
        for (int half = 0; half < 2; half++) {
            const float inv = 1.f / lrow[mt * 2 + half];
            int row = m0 + wm + mt * 16 + half * 8 + g;
            size_t doff = ((size_t)(b * Tt + row)) * Cc + h * Dd;
            #pragma unroll
            for (int nt = 0; nt < 8; nt++)
                *(uint32_t*)(g_ctx16 + doff + nt * 8 + tg * 2) =
                    packh2(o[mt][nt][half*2+0] * inv, o[mt][nt][half*2+1] * inv);
        }
}

// ---------------------------------------------------------------------------
extern "C" void kernel_launch(void* const* d_in, const int* in_sizes, int n_in,
                              void* d_out, int out_size)
{
    const float* x     = (const float*)d_in[0];
    const float* w_qkv = (const float*)d_in[1];
    const float* b_qkv = (const float*)d_in[2];
    const float* w_out = (const float*)d_in[3];
    const float* b_out = (const float*)d_in[4];
    float* out = (float*)d_out;

    constexpr int ATTN_SMEM = 18432 * 2;            // 36864 B
    constexpr int TG_SMEM   = 2 * 2 * 128 * 40 * 2; // 40960 B
    cudaFuncSetAttribute(attn_mma_kernel,
                         cudaFuncAttributeMaxDynamicSharedMemorySize, ATTN_SMEM);
    cudaFuncSetAttribute(tgemm_kernel<3072, 0>,
                         cudaFuncAttributeMaxDynamicSharedMemorySize, TG_SMEM);
    cudaFuncSetAttribute(tgemm_kernel<1024, 1>,
                         cudaFuncAttributeMaxDynamicSharedMemorySize, TG_SMEM);

    // 0) conversions
    conv_x_kernel<<<(size_t)NTOK * Cc / (256 * 4), 256>>>(x);
    {
        dim3 blk(32, 8);
        conv_w_kernel<0><<<dim3(3072 / 32, 1024 / 32), blk>>>(w_qkv);
        conv_w_kernel<1><<<dim3(1024 / 32, 1024 / 32), blk>>>(w_out);
    }
    // 1) QKV projection -> q/k/v fp16
    tgemm_kernel<3072, 0><<<dim3(3072 / 128, NTOK / 128), 256, TG_SMEM>>>(b_qkv, nullptr);
    // 2) flash attention -> ctx fp16
    attn_mma_kernel<<<dim3(16, Hh, Bb), 128, ATTN_SMEM>>>();
    // 3) output projection -> out (fp32)
    tgemm_kernel<1024, 1><<<dim3(1024 / 128, NTOK / 128), 256, TG_SMEM>>>(b_out, out);
}

// round 8
// speedup vs baseline: 10.2536x; 1.0116x over previous
#include <cuda_runtime.h>
#include <cuda_fp16.h>
#include <cstdint>

#define Bb 4
#define Tt 2048
#define Cc 1024
#define Hh 16
#define Dd 64
#define NTOK (Bb*Tt)   // 8192

// ---------------------------------------------------------------------------
// Scratch (__device__ globals)
// ---------------------------------------------------------------------------
__device__ __half g_x16[(size_t)NTOK*Cc];
__device__ __half g_ctx16[(size_t)NTOK*Cc];
__device__ __half g_q16[Bb*Hh*Tt*Dd], g_k16[Bb*Hh*Tt*Dd], g_v16[Bb*Hh*Tt*Dd];
__device__ __half g_wqkv16[3072*1024];
__device__ __half g_wout16[1024*1024];

// ---------------------------------------------------------------------------
// helpers
// ---------------------------------------------------------------------------
__device__ __forceinline__ uint32_t smem_u32(const void* p) {
    uint32_t a;
    asm("{ .reg .u64 t; cvta.to.shared.u64 t, %1; cvt.u32.u64 %0, t; }"
        : "=r"(a) : "l"(p));
    return a;
}
__device__ __forceinline__ void ldsm_x4(uint32_t addr, uint32_t& r0, uint32_t& r1,
                                        uint32_t& r2, uint32_t& r3) {
    asm volatile("ldmatrix.sync.aligned.m8n8.x4.shared.b16 {%0,%1,%2,%3}, [%4];"
                 : "=r"(r0), "=r"(r1), "=r"(r2), "=r"(r3) : "r"(addr));
}
__device__ __forceinline__ void ldsm_x4_t(uint32_t addr, uint32_t& r0, uint32_t& r1,
                                          uint32_t& r2, uint32_t& r3) {
    asm volatile("ldmatrix.sync.aligned.m8n8.x4.trans.shared.b16 {%0,%1,%2,%3}, [%4];"
                 : "=r"(r0), "=r"(r1), "=r"(r2), "=r"(r3) : "r"(addr));
}
__device__ __forceinline__ void mma_f16(float* d, const uint32_t* a, const uint32_t* b) {
    asm volatile(
        "mma.sync.aligned.m16n8k16.row.col.f32.f16.f16.f32 "
        "{%0,%1,%2,%3}, {%4,%5,%6,%7}, {%8,%9}, {%0,%1,%2,%3};"
        : "+f"(d[0]), "+f"(d[1]), "+f"(d[2]), "+f"(d[3])
        : "r"(a[0]), "r"(a[1]), "r"(a[2]), "r"(a[3]), "r"(b[0]), "r"(b[1]));
}
__device__ __forceinline__ uint32_t packh2(float x, float y) {
    __half2 h = __floats2half2_rn(x, y);
    return *(uint32_t*)&h;
}
__device__ __forceinline__ void cpa16(uint32_t dst, const void* src) {
    asm volatile("cp.async.ca.shared.global [%0], [%1], 16;" :: "r"(dst), "l"(src));
}
#define CP_COMMIT() asm volatile("cp.async.commit_group;" ::: "memory")
#define CP_WAIT(n)  asm volatile("cp.async.wait_group %0;" :: "n"(n) : "memory")

// ---------------------------------------------------------------------------
// x fp32 -> fp16
// ---------------------------------------------------------------------------
__global__ __launch_bounds__(256) void conv_x_kernel(const float* __restrict__ x)
{
    size_t i = ((size_t)blockIdx.x * 256 + threadIdx.x) * 4;
    float4 v = *(const float4*)(x + i);
    uint2 u;
    u.x = packh2(v.x, v.y);
    u.y = packh2(v.z, v.w);
    *(uint2*)(g_x16 + i) = u;
}

// ---------------------------------------------------------------------------
// Weight transpose + fp16: w[1024][N] -> Wt[N][1024]
// ---------------------------------------------------------------------------
template<int MODE>
__global__ __launch_bounds__(256) void conv_w_kernel(const float* __restrict__ w)
{
    constexpr int N = (MODE == 0) ? 3072 : 1024;
    __half* th = (MODE == 0) ? g_wqkv16 : g_wout16;
    __shared__ float tile[32][33];
    const int n0 = blockIdx.x * 32, k0 = blockIdx.y * 32;
    const int tx = threadIdx.x, ty = threadIdx.y;
    #pragma unroll
    for (int i = 0; i < 4; i++) {
        int k = ty + i * 8;
        tile[k][tx] = w[(size_t)(k0 + k) * N + n0 + tx];
    }
    __syncthreads();
    #pragma unroll
    for (int i = 0; i < 4; i++) {
        int r = ty + i * 8;
        th[(size_t)(n0 + r) * 1024 + k0 + tx] = __float2half_rn(tile[tx][r]);
    }
}

// ---------------------------------------------------------------------------
// fp16 HMMA GEMM: CTA 128x128, 4 warps (2Mx2N), warp tile 64x64.
// Per k16: 4 A-ldsm + 4 B-ldsm -> 32 mma (ratio 4.0). BK=32, 3-stage cp.async.
// MODE 0: scatter to q/k/v fp16 (q pre-scaled). MODE 1: dense fp32 out.
// ---------------------------------------------------------------------------
template<int N, int MODE>
__global__ __launch_bounds__(128, 2) void tgemm_kernel(
    const float* __restrict__ bias, float* __restrict__ Cout)
{
    extern __shared__ __half sm[];
    constexpr int LDS = 40;
    constexpr uint32_t T_A = 0, T_B = 128*LDS;
    constexpr uint32_t STAGE = 2*128*LDS;           // halves per stage
    constexpr int NSTAGE = 3;

    const __half* A = (MODE == 0) ? g_x16 : g_ctx16;
    const __half* W = (MODE == 0) ? g_wqkv16 : g_wout16;

    const int tid  = threadIdx.x;
    const int wid  = tid >> 5, lane = tid & 31;
    const int wm   = (wid & 1) * 64;
    const int wn   = (wid >> 1) * 64;
    const int lr   = lane & 15, lc = (lane >> 4) * 8;
    const int n0   = blockIdx.x * 128, m0 = blockIdx.y * 128;
    const uint32_t smB = smem_u32(sm);

    const int ldr = tid >> 2, ldc = tid & 3;        // 32 rows x 4 16B-chunks

    float acc[4][8][4];
    #pragma unroll
    for (int i = 0; i < 4; i++)
        #pragma unroll
        for (int j = 0; j < 8; j++)
            #pragma unroll
            for (int c = 0; c < 4; c++) acc[i][j][c] = 0.f;

    auto load_chunk = [&](int ch) {
        const int k0 = ch * 32;
        const uint32_t sb = smB + (ch % NSTAGE) * STAGE * 2;
        #pragma unroll
        for (int i = 0; i < 4; i++) {
            int r = ldr + i * 32;
            uint32_t doff = (uint32_t)(r * LDS + ldc * 8) * 2;
            cpa16(sb + T_A*2 + doff, A + (size_t)(m0 + r) * 1024 + k0 + ldc * 8);
            cpa16(sb + T_B*2 + doff, W + (size_t)(n0 + r) * 1024 + k0 + ldc * 8);
        }
        CP_COMMIT();
    };

    load_chunk(0);
    load_chunk(1);

    for (int ch = 0; ch < 32; ch++) {
        if (ch + 2 < 32) { load_chunk(ch + 2); CP_WAIT(2); }
        else             { CP_WAIT(0); }
        __syncthreads();

        const uint32_t sb = smB + (ch % NSTAGE) * STAGE * 2;
        const uint32_t aB = sb + T_A*2, bB = sb + T_B*2;

        #pragma unroll
        for (int half = 0; half < 2; half++) {
            const int kk = half * 16;
            uint32_t a[4][4], b[8][2];
            #pragma unroll
            for (int mt = 0; mt < 4; mt++) {
                uint32_t off = (uint32_t)((wm + mt * 16 + lr) * LDS + kk + lc) * 2;
                ldsm_x4(aB + off, a[mt][0], a[mt][1], a[mt][2], a[mt][3]);
            }
            #pragma unroll
            for (int np = 0; np < 4; np++) {
                uint32_t off = (uint32_t)((wn + np * 16 + lr) * LDS + kk + lc) * 2;
                uint32_t r0, r1, r2, r3;
                ldsm_x4(bB + off, r0, r1, r2, r3);
                b[np*2+0][0] = r0; b[np*2+0][1] = r2;
                b[np*2+1][0] = r1; b[np*2+1][1] = r3;
            }
            #pragma unroll
            for (int mt = 0; mt < 4; mt++)
                #pragma unroll
                for (int nt = 0; nt < 8; nt++)
                    mma_f16(acc[mt][nt], a[mt], b[nt]);
        }
        __syncthreads();
    }

    const int g = lane >> 2, tg = lane & 3;
    #pragma unroll
    for (int mt = 0; mt < 4; mt++)
        #pragma unroll
        for (int nt = 0; nt < 8; nt++) {
            int n = n0 + wn + nt * 8 + tg * 2;
            float bx = __ldg(bias + n), by = __ldg(bias + n + 1);
            #pragma unroll
            for (int hrow = 0; hrow < 2; hrow++) {
                int m = m0 + wm + mt * 16 + g + hrow * 8;
                float vx = acc[mt][nt][hrow * 2 + 0] + bx;
                float vy = acc[mt][nt][hrow * 2 + 1] + by;
                if (MODE == 0) {
                    int s   = n >> 10;
                    int rem = n & 1023;
                    int hh  = rem >> 6, dd = rem & 63;
                    int bi  = m >> 11, t = m & 2047;
                    if (s == 0) { vx *= 0.125f; vy *= 0.125f; }  // q pre-scale
                    __half* dst = (s == 0) ? g_q16 : (s == 1) ? g_k16 : g_v16;
                    size_t off = (((size_t)(bi * Hh + hh)) * Tt + t) * Dd + dd;
                    *(uint32_t*)(dst + off) = packh2(vx, vy);
                } else {
                    float2 o; o.x = vx; o.y = vy;
                    *(float2*)(Cout + (size_t)m * N + n) = o;
                }
            }
        }
}

// ---------------------------------------------------------------------------
// Flash attention, single fp16 mma path (unchanged from R7).
// ---------------------------------------------------------------------------
__global__ __launch_bounds__(128, 2) void attn_mma_kernel()
{
    extern __shared__ __half sm[];
    __half* Qs = sm;                 // 128*72
    __half* Ks = sm + 9216;          // 64*72
    __half* Vs = sm + 13824;         // 64*72

    const int tid = threadIdx.x, wid = tid >> 5, lane = tid & 31;
    const int qt = 15 - blockIdx.x;
    const int h = blockIdx.y, b = blockIdx.z;
    const int m0 = qt * 128;
    const size_t base = ((size_t)(b * Hh + h)) * Tt * Dd;

    #pragma unroll
    for (int i = 0; i < 8; i++) {
        int id = tid + i * 128;
        int r = id >> 3, c = id & 7;
        *(float4*)&Qs[r * 72 + c * 8] = *(const float4*)&g_q16[base + (size_t)(m0 + r) * Dd + c * 8];
    }

    const int wm = wid * 32;
    const int lr = lane & 15, lc = (lane >> 4) * 8;
    const int g = lane >> 2, tg = lane & 3;
    const uint32_t QB = smem_u32(Qs), KB = smem_u32(Ks), VB = smem_u32(Vs);

    float o[2][8][4];
    #pragma unroll
    for (int mt = 0; mt < 2; mt++)
        #pragma unroll
        for (int nt = 0; nt < 8; nt++)
            #pragma unroll
            for (int c = 0; c < 4; c++) o[mt][nt][c] = 0.f;
    float mrow[4] = {-1e30f, -1e30f, -1e30f, -1e30f};
    float lrow[4] = {0.f, 0.f, 0.f, 0.f};

    const int ntiles = 2 * qt + 2;
    for (int kt = 0; kt < ntiles; kt++) {
        #pragma unroll
        for (int i = 0; i < 4; i++) {
            int id = tid + i * 128;
            int r = id >> 3, c = id & 7;
            size_t src = base + (size_t)(kt * 64 + r) * Dd + c * 8;
            *(float4*)&Ks[r * 72 + c * 8] = *(const float4*)&g_k16[src];
            *(float4*)&Vs[r * 72 + c * 8] = *(const float4*)&g_v16[src];
        }
        __syncthreads();

        float s[2][8][4];
        #pragma unroll
        for (int mt = 0; mt < 2; mt++)
            #pragma unroll
            for (int nt = 0; nt < 8; nt++)
                #pragma unroll
                for (int c = 0; c < 4; c++) s[mt][nt][c] = 0.f;

        #pragma unroll
        for (int ks = 0; ks < 4; ks++) {
            uint32_t q[2][4];
            #pragma unroll
            for (int mt = 0; mt < 2; mt++) {
                uint32_t off = (uint32_t)((wm + mt * 16 + lr) * 72 + ks * 16 + lc) * 2;
                ldsm_x4(QB + off, q[mt][0], q[mt][1], q[mt][2], q[mt][3]);
            }
            uint32_t k[8][2];
            #pragma unroll
            for (int ng = 0; ng < 4; ng++) {
                uint32_t off = (uint32_t)((ng * 16 + lr) * 72 + ks * 16 + lc) * 2;
                uint32_t r0, r1, r2, r3;
                ldsm_x4(KB + off, r0, r1, r2, r3);
                k[ng*2+0][0] = r0; k[ng*2+0][1] = r2;
                k[ng*2+1][0] = r1; k[ng*2+1][1] = r3;
            }
            #pragma unroll
            for (int mt = 0; mt < 2; mt++)
                #pragma unroll
                for (int nt = 0; nt < 8; nt++)
                    mma_f16(s[mt][nt], q[mt], k[nt]);
        }

        if (kt >= 2 * qt) {
            #pragma unroll
            for (int mt = 0; mt < 2; mt++)
                #pragma unroll
                for (int nt = 0; nt < 8; nt++)
                    #pragma unroll
                    for (int c = 0; c < 4; c++) {
                        int row = m0 + wm + mt * 16 + (c >> 1) * 8 + g;
                        int kg  = kt * 64 + nt * 8 + tg * 2 + (c & 1);
                        if (kg > row) s[mt][nt][c] = -1e30f;
                    }
        }

        #pragma unroll
        for (int mt = 0; mt < 2; mt++)
            #pragma unroll
            for (int half = 0; half < 2; half++) {
                const int slot = mt * 2 + half;
                float mx = -1e30f;
                #pragma unroll
                for (int nt = 0; nt < 8; nt++)
                    mx = fmaxf(mx, fmaxf(s[mt][nt][half*2], s[mt][nt][half*2+1]));
                mx = fmaxf(mx, __shfl_xor_sync(0xffffffffu, mx, 1));
                mx = fmaxf(mx, __shfl_xor_sync(0xffffffffu, mx, 2));
                float Mn = fmaxf(mrow[slot], mx);
                float f = __expf(mrow[slot] - Mn);
                mrow[slot] = Mn;
                lrow[slot] *= f;
                float ps = 0.f;
                #pragma unroll
                for (int nt = 0; nt < 8; nt++) {
                    float p0 = __expf(s[mt][nt][half*2+0] - Mn);
                    float p1 = __expf(s[mt][nt][half*2+1] - Mn);
                    s[mt][nt][half*2+0] = p0;
                    s[mt][nt][half*2+1] = p1;
                    ps += p0 + p1;
                    o[mt][nt][half*2+0] *= f;
                    o[mt][nt][half*2+1] *= f;
                }
                ps += __shfl_xor_sync(0xffffffffu, ps, 1);
                ps += __shfl_xor_sync(0xffffffffu, ps, 2);
                lrow[slot] += ps;
            }

        #pragma unroll
        for (int ksp = 0; ksp < 4; ksp++) {
            uint32_t p[2][4];
            #pragma unroll
            for (int mt = 0; mt < 2; mt++) {
                p[mt][0] = packh2(s[mt][2*ksp+0][0], s[mt][2*ksp+0][1]);
                p[mt][1] = packh2(s[mt][2*ksp+0][2], s[mt][2*ksp+0][3]);
                p[mt][2] = packh2(s[mt][2*ksp+1][0], s[mt][2*ksp+1][1]);
                p[mt][3] = packh2(s[mt][2*ksp+1][2], s[mt][2*ksp+1][3]);
            }
            uint32_t v[8][2];
            #pragma unroll
            for (int ng = 0; ng < 4; ng++) {
                uint32_t off = (uint32_t)((ksp * 16 + lr) * 72 + ng * 16 + lc) * 2;
                uint32_t r0, r1, r2, r3;
                ldsm_x4_t(VB + off, r0, r1, r2, r3);
                v[ng*2+0][0] = r0; v[ng*2+0][1] = r1;
                v[ng*2+1][0] = r2; v[ng*2+1][1] = r3;
            }
            #pragma unroll
            for (int mt = 0; mt < 2; mt++)
                #pragma unroll
                for (int nt = 0; nt < 8; nt++)
                    mma_f16(o[mt][nt], p[mt], v[nt]);
        }
        __syncthreads();
    }

    #pragma unroll
    for (int mt = 0; mt < 2; mt++)
        #pragma unroll
        for (int half = 0; half < 2; half++) {
            const float inv = 1.f / lrow[mt * 2 + half];
            int row = m0 + wm + mt * 16 + half * 8 + g;
            size_t doff = ((size_t)(b * Tt + row)) * Cc + h * Dd;
            #pragma unroll
            for (int nt = 0; nt < 8; nt++)
                *(uint32_t*)(g_ctx16 + doff + nt * 8 + tg * 2) =
                    packh2(o[mt][nt][half*2+0] * inv, o[mt][nt][half*2+1] * inv);
        }
}

// ---------------------------------------------------------------------------
extern "C" void kernel_launch(void* const* d_in, const int* in_sizes, int n_in,
                              void* d_out, int out_size)
{
    const float* x     = (const float*)d_in[0];
    const float* w_qkv = (const float*)d_in[1];
    const float* b_qkv = (const float*)d_in[2];
    const float* w_out = (const float*)d_in[3];
    const float* b_out = (const float*)d_in[4];
    float* out = (float*)d_out;

    constexpr int ATTN_SMEM = 18432 * 2;            // 36864 B
    constexpr int TG_SMEM   = 3 * 2 * 128 * 40 * 2; // 61440 B (3 stages)
    cudaFuncSetAttribute(attn_mma_kernel,
                         cudaFuncAttributeMaxDynamicSharedMemorySize, ATTN_SMEM);
    cudaFuncSetAttribute(tgemm_kernel<3072, 0>,
                         cudaFuncAttributeMaxDynamicSharedMemorySize, TG_SMEM);
    cudaFuncSetAttribute(tgemm_kernel<1024, 1>,
                         cudaFuncAttributeMaxDynamicSharedMemorySize, TG_SMEM);

    // 0) conversions
    conv_x_kernel<<<(size_t)NTOK * Cc / (256 * 4), 256>>>(x);
    {
        dim3 blk(32, 8);
        conv_w_kernel<0><<<dim3(3072 / 32, 1024 / 32), blk>>>(w_qkv);
        conv_w_kernel<1><<<dim3(1024 / 32, 1024 / 32), blk>>>(w_out);
    }
    // 1) QKV projection -> q/k/v fp16
    tgemm_kernel<3072, 0><<<dim3(3072 / 128, NTOK / 128), 128, TG_SMEM>>>(b_qkv, nullptr);
    // 2) flash attention -> ctx fp16
    attn_mma_kernel<<<dim3(16, Hh, Bb), 128, ATTN_SMEM>>>();
    // 3) output projection -> out (fp32)
    tgemm_kernel<1024, 1><<<dim3(1024 / 128, NTOK / 128), 128, TG_SMEM>>>(b_out, out);
}

// round 10
// speedup vs baseline: 10.2685x; 1.0014x over previous
#include <cuda_runtime.h>
#include <cuda_fp16.h>
#include <cstdint>

#define Bb 4
#define Tt 2048
#define Cc 1024
#define Hh 16
#define Dd 64
#define NTOK (Bb*Tt)   // 8192

// ---------------------------------------------------------------------------
// Scratch (__device__ globals)
// ---------------------------------------------------------------------------
__device__ __half g_x16[(size_t)NTOK*Cc];
__device__ __half g_ctx16[(size_t)NTOK*Cc];
__device__ __half g_q16[Bb*Hh*Tt*Dd], g_k16[Bb*Hh*Tt*Dd], g_v16[Bb*Hh*Tt*Dd];
__device__ __half g_wqkv16[3072*1024];
__device__ __half g_wout16[1024*1024];

// ---------------------------------------------------------------------------
// helpers
// ---------------------------------------------------------------------------
__device__ __forceinline__ uint32_t smem_u32(const void* p) {
    uint32_t a;
    asm("{ .reg .u64 t; cvta.to.shared.u64 t, %1; cvt.u32.u64 %0, t; }"
        : "=r"(a) : "l"(p));
    return a;
}
__device__ __forceinline__ void ldsm_x4(uint32_t addr, uint32_t& r0, uint32_t& r1,
                                        uint32_t& r2, uint32_t& r3) {
    asm volatile("ldmatrix.sync.aligned.m8n8.x4.shared.b16 {%0,%1,%2,%3}, [%4];"
                 : "=r"(r0), "=r"(r1), "=r"(r2), "=r"(r3) : "r"(addr));
}
__device__ __forceinline__ void ldsm_x4_t(uint32_t addr, uint32_t& r0, uint32_t& r1,
                                          uint32_t& r2, uint32_t& r3) {
    asm volatile("ldmatrix.sync.aligned.m8n8.x4.trans.shared.b16 {%0,%1,%2,%3}, [%4];"
                 : "=r"(r0), "=r"(r1), "=r"(r2), "=r"(r3) : "r"(addr));
}
__device__ __forceinline__ void mma_f16(float* d, const uint32_t* a, const uint32_t* b) {
    asm volatile(
        "mma.sync.aligned.m16n8k16.row.col.f32.f16.f16.f32 "
        "{%0,%1,%2,%3}, {%4,%5,%6,%7}, {%8,%9}, {%0,%1,%2,%3};"
        : "+f"(d[0]), "+f"(d[1]), "+f"(d[2]), "+f"(d[3])
        : "r"(a[0]), "r"(a[1]), "r"(a[2]), "r"(a[3]), "r"(b[0]), "r"(b[1]));
}
__device__ __forceinline__ uint32_t packh2(float x, float y) {
    __half2 h = __floats2half2_rn(x, y);
    return *(uint32_t*)&h;
}
__device__ __forceinline__ void cpa16(uint32_t dst, const void* src) {
    asm volatile("cp.async.cg.shared.global [%0], [%1], 16;" :: "r"(dst), "l"(src));
}
#define CP_COMMIT() asm volatile("cp.async.commit_group;" ::: "memory")
#define CP_WAIT(n)  asm volatile("cp.async.wait_group %0;" :: "n"(n) : "memory")

// ---------------------------------------------------------------------------
// x fp32 -> fp16
// ---------------------------------------------------------------------------
__global__ __launch_bounds__(256) void conv_x_kernel(const float* __restrict__ x)
{
    size_t i = ((size_t)blockIdx.x * 256 + threadIdx.x) * 4;
    float4 v = *(const float4*)(x + i);
    uint2 u;
    u.x = packh2(v.x, v.y);
    u.y = packh2(v.z, v.w);
    *(uint2*)(g_x16 + i) = u;
}

// ---------------------------------------------------------------------------
// Weight transpose + fp16: w[1024][N] -> Wt[N][1024]
// ---------------------------------------------------------------------------
template<int MODE>
__global__ __launch_bounds__(256) void conv_w_kernel(const float* __restrict__ w)
{
    constexpr int N = (MODE == 0) ? 3072 : 1024;
    __half* th = (MODE == 0) ? g_wqkv16 : g_wout16;
    __shared__ float tile[32][33];
    const int n0 = blockIdx.x * 32, k0 = blockIdx.y * 32;
    const int tx = threadIdx.x, ty = threadIdx.y;
    #pragma unroll
    for (int i = 0; i < 4; i++) {
        int k = ty + i * 8;
        tile[k][tx] = w[(size_t)(k0 + k) * N + n0 + tx];
    }
    __syncthreads();
    #pragma unroll
    for (int i = 0; i < 4; i++) {
        int r = ty + i * 8;
        th[(size_t)(n0 + r) * 1024 + k0 + tx] = __float2half_rn(tile[tx][r]);
    }
}

// ---------------------------------------------------------------------------
// fp16 HMMA GEMM: CTA 128x128, 4 warps (2Mx2N), warp tile 64x64.
// BK=64, 2-stage cp.async, ONE __syncthreads per chunk.
// MODE 0: scatter to q/k/v fp16 (q pre-scaled). MODE 1: dense fp32 out.
// ---------------------------------------------------------------------------
template<int N, int MODE>
__global__ __launch_bounds__(128, 2) void tgemm_kernel(
    const float* __restrict__ bias, float* __restrict__ Cout)
{
    extern __shared__ __half sm[];
    constexpr int LDS = 72;
    constexpr uint32_t T_A = 0, T_B = 128*LDS;      // halves
    constexpr uint32_t STAGE = 2*128*LDS;           // halves per stage (18432)
    constexpr int NCH = 16;                          // 1024 / 64

    const __half* A = (MODE == 0) ? g_x16 : g_ctx16;
    const __half* W = (MODE == 0) ? g_wqkv16 : g_wout16;

    const int tid  = threadIdx.x;
    const int wid  = tid >> 5, lane = tid & 31;
    const int wm   = (wid & 1) * 64;
    const int wn   = (wid >> 1) * 64;
    const int lr   = lane & 15, lc = (lane >> 4) * 8;
    const int n0   = blockIdx.x * 128, m0 = blockIdx.y * 128;
    const uint32_t smB = smem_u32(sm);

    const int ldr = tid >> 3, ldc = tid & 7;        // 16 rows x 8 16B-chunks

    float acc[4][8][4];
    #pragma unroll
    for (int i = 0; i < 4; i++)
        #pragma unroll
        for (int j = 0; j < 8; j++)
            #pragma unroll
            for (int c = 0; c < 4; c++) acc[i][j][c] = 0.f;

    auto load_chunk = [&](int ch) {
        const int k0 = ch * 64;
        const uint32_t sb = smB + (ch & 1) * STAGE * 2;
        #pragma unroll
        for (int i = 0; i < 8; i++) {
            int r = ldr + i * 16;
            uint32_t doff = (uint32_t)(r * LDS + ldc * 8) * 2;
            cpa16(sb + T_A*2 + doff, A + (size_t)(m0 + r) * 1024 + k0 + ldc * 8);
            cpa16(sb + T_B*2 + doff, W + (size_t)(n0 + r) * 1024 + k0 + ldc * 8);
        }
        CP_COMMIT();
    };

    load_chunk(0);

    for (int ch = 0; ch < NCH; ch++) {
        CP_WAIT(0);
        __syncthreads();           // tile ch ready for all; prev compute done
        if (ch + 1 < NCH) load_chunk(ch + 1);

        const uint32_t sb = smB + (ch & 1) * STAGE * 2;
        const uint32_t aB = sb + T_A*2, bB = sb + T_B*2;

        #pragma unroll
        for (int ks = 0; ks < 4; ks++) {
            const int kk = ks * 16;
            uint32_t a[4][4], b[8][2];
            #pragma unroll
            for (int mt = 0; mt < 4; mt++) {
                uint32_t off = (uint32_t)((wm + mt * 16 + lr) * LDS + kk + lc) * 2;
                ldsm_x4(aB + off, a[mt][0], a[mt][1], a[mt][2], a[mt][3]);
            }
            #pragma unroll
            for (int np = 0; np < 4; np++) {
                uint32_t off = (uint32_t)((wn + np * 16 + lr) * LDS + kk + lc) * 2;
                uint32_t r0, r1, r2, r3;
                ldsm_x4(bB + off, r0, r1, r2, r3);
                b[np*2+0][0] = r0; b[np*2+0][1] = r2;
                b[np*2+1][0] = r1; b[np*2+1][1] = r3;
            }
            #pragma unroll
            for (int mt = 0; mt < 4; mt++)
                #pragma unroll
                for (int nt = 0; nt < 8; nt++)
                    mma_f16(acc[mt][nt], a[mt], b[nt]);
        }
    }

    const int g = lane >> 2, tg = lane & 3;
    #pragma unroll
    for (int mt = 0; mt < 4; mt++)
        #pragma unroll
        for (int nt = 0; nt < 8; nt++) {
            int n = n0 + wn + nt * 8 + tg * 2;
            float bx = __ldg(bias + n), by = __ldg(bias + n + 1);
            #pragma unroll
            for (int hrow = 0; hrow < 2; hrow++) {
                int m = m0 + wm + mt * 16 + g + hrow * 8;
                float vx = acc[mt][nt][hrow * 2 + 0] + bx;
                float vy = acc[mt][nt][hrow * 2 + 1] + by;
                if (MODE == 0) {
                    int s   = n >> 10;
                    int rem = n & 1023;
                    int hh  = rem >> 6, dd = rem & 63;
                    int bi  = m >> 11, t = m & 2047;
                    if (s == 0) { vx *= 0.125f; vy *= 0.125f; }  // q pre-scale
                    __half* dst = (s == 0) ? g_q16 : (s == 1) ? g_k16 : g_v16;
                    size_t off = (((size_t)(bi * Hh + hh)) * Tt + t) * Dd + dd;
                    *(uint32_t*)(dst + off) = packh2(vx, vy);
                } else {
                    float2 o; o.x = vx; o.y = vy;
                    *(float2*)(Cout + (size_t)m * N + n) = o;
                }
            }
        }
}

// ---------------------------------------------------------------------------
// Flash attention, fp16 mma, cp.async 2-stage K/V pipeline,
// ONE __syncthreads per 64-key tile.
// smem: Q 128x72 | stage0 {K 64x72, V 64x72} | stage1 {K, V}
// ---------------------------------------------------------------------------
__global__ __launch_bounds__(128, 2) void attn_mma_kernel()
{
    extern __shared__ __half sm[];
    __half* Qs = sm;                            // 9216 halves
    constexpr uint32_t ST_K = 9216, ST_V = 13824;   // stage0 offsets (halves)
    constexpr uint32_t STAGE = 9216;                // halves per stage (K+V)

    const int tid = threadIdx.x, wid = tid >> 5, lane = tid & 31;
    const int qt = 15 - blockIdx.x;
    const int h = blockIdx.y, b = blockIdx.z;
    const int m0 = qt * 128;
    const size_t base = ((size_t)(b * Hh + h)) * Tt * Dd;
    const uint32_t smB = smem_u32(sm);

    // stage Q (plain stores; covered by first loop sync)
    #pragma unroll
    for (int i = 0; i < 8; i++) {
        int id = tid + i * 128;
        int r = id >> 3, c = id & 7;
        *(float4*)&Qs[r * 72 + c * 8] = *(const float4*)&g_q16[base + (size_t)(m0 + r) * Dd + c * 8];
    }

    const int wm = wid * 32;
    const int lr = lane & 15, lc = (lane >> 4) * 8;
    const int g = lane >> 2, tg = lane & 3;
    const uint32_t QB = smB;

    const int ldr = tid >> 3, ldc = tid & 7;    // 16 rows x 8 chunks
    auto load_tile = [&](int kt) {
        const uint32_t sb = smB + ((kt & 1) * STAGE + ST_K) * 2;
        #pragma unroll
        for (int i = 0; i < 4; i++) {
            int r = ldr + i * 16;
            uint32_t doff = (uint32_t)(r * 72 + ldc * 8) * 2;
            size_t src = base + (size_t)(kt * 64 + r) * Dd + ldc * 8;
            cpa16(sb + doff, &g_k16[src]);
            cpa16(sb + (ST_V - ST_K) * 2 + doff, &g_v16[src]);
        }
        CP_COMMIT();
    };

    float o[2][8][4];
    #pragma unroll
    for (int mt = 0; mt < 2; mt++)
        #pragma unroll
        for (int nt = 0; nt < 8; nt++)
            #pragma unroll
            for (int c = 0; c < 4; c++) o[mt][nt][c] = 0.f;
    float mrow[4] = {-1e30f, -1e30f, -1e30f, -1e30f};
    float lrow[4] = {0.f, 0.f, 0.f, 0.f};

    const int ntiles = 2 * qt + 2;
    load_tile(0);

    for (int kt = 0; kt < ntiles; kt++) {
        CP_WAIT(0);
        __syncthreads();
        if (kt + 1 < ntiles) load_tile(kt + 1);

        const uint32_t KB = smB + ((kt & 1) * STAGE + ST_K) * 2;
        const uint32_t VB = smB + ((kt & 1) * STAGE + ST_V) * 2;

        float s[2][8][4];
        #pragma unroll
        for (int mt = 0; mt < 2; mt++)
            #pragma unroll
            for (int nt = 0; nt < 8; nt++)
                #pragma unroll
                for (int c = 0; c < 4; c++) s[mt][nt][c] = 0.f;

        #pragma unroll
        for (int ks = 0; ks < 4; ks++) {
            uint32_t q[2][4];
            #pragma unroll
            for (int mt = 0; mt < 2; mt++) {
                uint32_t off = (uint32_t)((wm + mt * 16 + lr) * 72 + ks * 16 + lc) * 2;
                ldsm_x4(QB + off, q[mt][0], q[mt][1], q[mt][2], q[mt][3]);
            }
            uint32_t k[8][2];
            #pragma unroll
            for (int ng = 0; ng < 4; ng++) {
                uint32_t off = (uint32_t)((ng * 16 + lr) * 72 + ks * 16 + lc) * 2;
                uint32_t r0, r1, r2, r3;
                ldsm_x4(KB + off, r0, r1, r2, r3);
                k[ng*2+0][0] = r0; k[ng*2+0][1] = r2;
                k[ng*2+1][0] = r1; k[ng*2+1][1] = r3;
            }
            #pragma unroll
            for (int mt = 0; mt < 2; mt++)
                #pragma unroll
                for (int nt = 0; nt < 8; nt++)
                    mma_f16(s[mt][nt], q[mt], k[nt]);
        }

        if (kt >= 2 * qt) {
            #pragma unroll
            for (int mt = 0; mt < 2; mt++)
                #pragma unroll
                for (int nt = 0; nt < 8; nt++)
                    #pragma unroll
                    for (int c = 0; c < 4; c++) {
                        int row = m0 + wm + mt * 16 + (c >> 1) * 8 + g;
                        int kg  = kt * 64 + nt * 8 + tg * 2 + (c & 1);
                        if (kg > row) s[mt][nt][c] = -1e30f;
                    }
        }

        #pragma unroll
        for (int mt = 0; mt < 2; mt++)
            #pragma unroll
            for (int half = 0; half < 2; half++) {
                const int slot = mt * 2 + half;
                float mx = -1e30f;
                #pragma unroll
                for (int nt = 0; nt < 8; nt++)
                    mx = fmaxf(mx, fmaxf(s[mt][nt][half*2], s[mt][nt][half*2+1]));
                mx = fmaxf(mx, __shfl_xor_sync(0xffffffffu, mx, 1));
                mx = fmaxf(mx, __shfl_xor_sync(0xffffffffu, mx, 2));
                float Mn = fmaxf(mrow[slot], mx);
                float f = __expf(mrow[slot] - Mn);
                mrow[slot] = Mn;
                lrow[slot] *= f;
                float ps = 0.f;
                #pragma unroll
                for (int nt = 0; nt < 8; nt++) {
                    float p0 = __expf(s[mt][nt][half*2+0] - Mn);
                    float p1 = __expf(s[mt][nt][half*2+1] - Mn);
                    s[mt][nt][half*2+0] = p0;
                    s[mt][nt][half*2+1] = p1;
                    ps += p0 + p1;
                    o[mt][nt][half*2+0] *= f;
                    o[mt][nt][half*2+1] *= f;
                }
                ps += __shfl_xor_sync(0xffffffffu, ps, 1);
                ps += __shfl_xor_sync(0xffffffffu, ps, 2);
                lrow[slot] += ps;
            }

        #pragma unroll
        for (int ksp = 0; ksp < 4; ksp++) {
            uint32_t p[2][4];
            #pragma unroll
            for (int mt = 0; mt < 2; mt++) {
                p[mt][0] = packh2(s[mt][2*ksp+0][0], s[mt][2*ksp+0][1]);
                p[mt][1] = packh2(s[mt][2*ksp+0][2], s[mt][2*ksp+0][3]);
                p[mt][2] = packh2(s[mt][2*ksp+1][0], s[mt][2*ksp+1][1]);
                p[mt][3] = packh2(s[mt][2*ksp+1][2], s[mt][2*ksp+1][3]);
            }
            uint32_t v[8][2];
            #pragma unroll
            for (int ng = 0; ng < 4; ng++) {
                uint32_t off = (uint32_t)((ksp * 16 + lr) * 72 + ng * 16 + lc) * 2;
                uint32_t r0, r1, r2, r3;
                ldsm_x4_t(VB + off, r0, r1, r2, r3);
                v[ng*2+0][0] = r0; v[ng*2+0][1] = r1;
                v[ng*2+1][0] = r2; v[ng*2+1][1] = r3;
            }
            #pragma unroll
            for (int mt = 0; mt < 2; mt++)
                #pragma unroll
                for (int nt = 0; nt < 8; nt++)
                    mma_f16(o[mt][nt], p[mt], v[nt]);
        }
    }

    #pragma unroll
    for (int mt = 0; mt < 2; mt++)
        #pragma unroll
        for (int half = 0; half < 2; half++) {
            const float inv = 1.f / lrow[mt * 2 + half];
            int row = m0 + wm + mt * 16 + half * 8 + g;
            size_t doff = ((size_t)(b * Tt + row)) * Cc + h * Dd;
            #pragma unroll
            for (int nt = 0; nt < 8; nt++)
                *(uint32_t*)(g_ctx16 + doff + nt * 8 + tg * 2) =
                    packh2(o[mt][nt][half*2+0] * inv, o[mt][nt][half*2+1] * inv);
        }
}

// ---------------------------------------------------------------------------
extern "C" void kernel_launch(void* const* d_in, const int* in_sizes, int n_in,
                              void* d_out, int out_size)
{
    const float* x     = (const float*)d_in[0];
    const float* w_qkv = (const float*)d_in[1];
    const float* b_qkv = (const float*)d_in[2];
    const float* w_out = (const float*)d_in[3];
    const float* b_out = (const float*)d_in[4];
    float* out = (float*)d_out;

    constexpr int ATTN_SMEM = (9216 + 2 * 9216) * 2;    // 55296 B
    constexpr int TG_SMEM   = 2 * 2 * 128 * 72 * 2;     // 73728 B
    cudaFuncSetAttribute(attn_mma_kernel,
                         cudaFuncAttributeMaxDynamicSharedMemorySize, ATTN_SMEM);
    cudaFuncSetAttribute(tgemm_kernel<3072, 0>,
                         cudaFuncAttributeMaxDynamicSharedMemorySize, TG_SMEM);
    cudaFuncSetAttribute(tgemm_kernel<1024, 1>,
                         cudaFuncAttributeMaxDynamicSharedMemorySize, TG_SMEM);

    // 0) conversions
    conv_x_kernel<<<(size_t)NTOK * Cc / (256 * 4), 256>>>(x);
    {
        dim3 blk(32, 8);
        conv_w_kernel<0><<<dim3(3072 / 32, 1024 / 32), blk>>>(w_qkv);
        conv_w_kernel<1><<<dim3(1024 / 32, 1024 / 32), blk>>>(w_out);
    }
    // 1) QKV projection -> q/k/v fp16
    tgemm_kernel<3072, 0><<<dim3(3072 / 128, NTOK / 128), 128, TG_SMEM>>>(b_qkv, nullptr);
    // 2) flash attention -> ctx fp16
    attn_mma_kernel<<<dim3(16, Hh, Bb), 128, ATTN_SMEM>>>();
    // 3) output projection -> out (fp32)
    tgemm_kernel<1024, 1><<<dim3(1024 / 128, NTOK / 128), 128, TG_SMEM>>>(b_out, out);
}

// round 12
// speedup vs baseline: 10.3007x; 1.0031x over previous
#include <cuda_runtime.h>
#include <cuda_fp16.h>
#include <cstdint>

#define Bb 4
#define Tt 2048
#define Cc 1024
#define Hh 16
#define Dd 64
#define NTOK (Bb*Tt)   // 8192

// ---------------------------------------------------------------------------
// Scratch (__device__ globals)
// ---------------------------------------------------------------------------
__device__ __half g_x16[(size_t)NTOK*Cc];
__device__ __half g_ctx16[(size_t)NTOK*Cc];
__device__ __half g_q16[Bb*Hh*Tt*Dd], g_k16[Bb*Hh*Tt*Dd], g_v16[Bb*Hh*Tt*Dd];
__device__ __half g_wqkv16[3072*1024];
__device__ __half g_wout16[1024*1024];

// ---------------------------------------------------------------------------
// helpers
// ---------------------------------------------------------------------------
__device__ __forceinline__ uint32_t smem_u32(const void* p) {
    uint32_t a;
    asm("{ .reg .u64 t; cvta.to.shared.u64 t, %1; cvt.u32.u64 %0, t; }"
        : "=r"(a) : "l"(p));
    return a;
}
__device__ __forceinline__ void ldsm_x4(uint32_t addr, uint32_t& r0, uint32_t& r1,
                                        uint32_t& r2, uint32_t& r3) {
    asm volatile("ldmatrix.sync.aligned.m8n8.x4.shared.b16 {%0,%1,%2,%3}, [%4];"
                 : "=r"(r0), "=r"(r1), "=r"(r2), "=r"(r3) : "r"(addr));
}
__device__ __forceinline__ void ldsm_x4_t(uint32_t addr, uint32_t& r0, uint32_t& r1,
                                          uint32_t& r2, uint32_t& r3) {
    asm volatile("ldmatrix.sync.aligned.m8n8.x4.trans.shared.b16 {%0,%1,%2,%3}, [%4];"
                 : "=r"(r0), "=r"(r1), "=r"(r2), "=r"(r3) : "r"(addr));
}
__device__ __forceinline__ void mma_f16(float* d, const uint32_t* a, const uint32_t* b) {
    asm volatile(
        "mma.sync.aligned.m16n8k16.row.col.f32.f16.f16.f32 "
        "{%0,%1,%2,%3}, {%4,%5,%6,%7}, {%8,%9}, {%0,%1,%2,%3};"
        : "+f"(d[0]), "+f"(d[1]), "+f"(d[2]), "+f"(d[3])
        : "r"(a[0]), "r"(a[1]), "r"(a[2]), "r"(a[3]), "r"(b[0]), "r"(b[1]));
}
__device__ __forceinline__ uint32_t packh2(float x, float y) {
    __half2 h = __floats2half2_rn(x, y);
    return *(uint32_t*)&h;
}
__device__ __forceinline__ void cpa16(uint32_t dst, const void* src) {
    asm volatile("cp.async.cg.shared.global [%0], [%1], 16;" :: "r"(dst), "l"(src));
}
#define CP_COMMIT() asm volatile("cp.async.commit_group;" ::: "memory")
#define CP_WAIT(n)  asm volatile("cp.async.wait_group %0;" :: "n"(n) : "memory")

// ---------------------------------------------------------------------------
// x fp32 -> fp16
// ---------------------------------------------------------------------------
__global__ __launch_bounds__(256) void conv_x_kernel(const float* __restrict__ x)
{
    size_t i = ((size_t)blockIdx.x * 256 + threadIdx.x) * 4;
    float4 v = *(const float4*)(x + i);
    uint2 u;
    u.x = packh2(v.x, v.y);
    u.y = packh2(v.z, v.w);
    *(uint2*)(g_x16 + i) = u;
}

// ---------------------------------------------------------------------------
// Weight transpose + fp16: w[1024][N] -> Wt[N][1024]
// ---------------------------------------------------------------------------
template<int MODE>
__global__ __launch_bounds__(256) void conv_w_kernel(const float* __restrict__ w)
{
    constexpr int N = (MODE == 0) ? 3072 : 1024;
    __half* th = (MODE == 0) ? g_wqkv16 : g_wout16;
    __shared__ float tile[32][33];
    const int n0 = blockIdx.x * 32, k0 = blockIdx.y * 32;
    const int tx = threadIdx.x, ty = threadIdx.y;
    #pragma unroll
    for (int i = 0; i < 4; i++) {
        int k = ty + i * 8;
        tile[k][tx] = w[(size_t)(k0 + k) * N + n0 + tx];
    }
    __syncthreads();
    #pragma unroll
    for (int i = 0; i < 4; i++) {
        int r = ty + i * 8;
        th[(size_t)(n0 + r) * 1024 + k0 + tx] = __float2half_rn(tile[tx][r]);
    }
}

// ---------------------------------------------------------------------------
// fp16 HMMA GEMM: CTA 128x128, 4 warps (2Mx2N), warp tile 64x64.
// BK=64, 2-stage cp.async, ONE __syncthreads per chunk,
// EXPLICIT fragment double-buffering across ks (overlap ldsm with mma).
// MODE 0: scatter to q/k/v fp16 (q pre-scaled). MODE 1: dense fp32 out.
// ---------------------------------------------------------------------------
template<int N, int MODE>
__global__ __launch_bounds__(128, 2) void tgemm_kernel(
    const float* __restrict__ bias, float* __restrict__ Cout)
{
    extern __shared__ __half sm[];
    constexpr int LDS = 72;
    constexpr uint32_t T_A = 0, T_B = 128*LDS;      // halves
    constexpr uint32_t STAGE = 2*128*LDS;           // halves per stage (18432)
    constexpr int NCH = 16;                          // 1024 / 64

    const __half* A = (MODE == 0) ? g_x16 : g_ctx16;
    const __half* W = (MODE == 0) ? g_wqkv16 : g_wout16;

    const int tid  = threadIdx.x;
    const int wid  = tid >> 5, lane = tid & 31;
    const int wm   = (wid & 1) * 64;
    const int wn   = (wid >> 1) * 64;
    const int lr   = lane & 15, lc = (lane >> 4) * 8;
    const int n0   = blockIdx.x * 128, m0 = blockIdx.y * 128;
    const uint32_t smB = smem_u32(sm);

    const int ldr = tid >> 3, ldc = tid & 7;        // 16 rows x 8 16B-chunks

    float acc[4][8][4];
    #pragma unroll
    for (int i = 0; i < 4; i++)
        #pragma unroll
        for (int j = 0; j < 8; j++)
            #pragma unroll
            for (int c = 0; c < 4; c++) acc[i][j][c] = 0.f;

    auto load_chunk = [&](int ch) {
        const int k0 = ch * 64;
        const uint32_t sb = smB + (ch & 1) * STAGE * 2;
        #pragma unroll
        for (int i = 0; i < 8; i++) {
            int r = ldr + i * 16;
            uint32_t doff = (uint32_t)(r * LDS + ldc * 8) * 2;
            cpa16(sb + T_A*2 + doff, A + (size_t)(m0 + r) * 1024 + k0 + ldc * 8);
            cpa16(sb + T_B*2 + doff, W + (size_t)(n0 + r) * 1024 + k0 + ldc * 8);
        }
        CP_COMMIT();
    };

    // fragment load macro: kk = k offset in halves within tile
#define LOAD_FRAGS(kk, abuf, bbuf)                                            \
    do {                                                                      \
        _Pragma("unroll")                                                     \
        for (int mt = 0; mt < 4; mt++) {                                      \
            uint32_t off = (uint32_t)((wm + mt * 16 + lr) * LDS + (kk) + lc) * 2; \
            ldsm_x4(aB + off, abuf[mt][0], abuf[mt][1], abuf[mt][2], abuf[mt][3]); \
        }                                                                     \
        _Pragma("unroll")                                                     \
        for (int np = 0; np < 4; np++) {                                      \
            uint32_t off = (uint32_t)((wn + np * 16 + lr) * LDS + (kk) + lc) * 2; \
            uint32_t r0, r1, r2, r3;                                          \
            ldsm_x4(bB + off, r0, r1, r2, r3);                                \
            bbuf[np*2+0][0] = r0; bbuf[np*2+0][1] = r2;                       \
            bbuf[np*2+1][0] = r1; bbuf[np*2+1][1] = r3;                       \
        }                                                                     \
    } while (0)

    load_chunk(0);

    for (int ch = 0; ch < NCH; ch++) {
        CP_WAIT(0);
        __syncthreads();           // tile ch ready for all; prev compute done
        if (ch + 1 < NCH) load_chunk(ch + 1);

        const uint32_t sb = smB + (ch & 1) * STAGE * 2;
        const uint32_t aB = sb + T_A*2, bB = sb + T_B*2;

        uint32_t a[2][4][4], b[2][8][2];
        LOAD_FRAGS(0, a[0], b[0]);

        #pragma unroll
        for (int ks = 0; ks < 4; ks++) {
            const int cur = ks & 1, nxt = cur ^ 1;
            if (ks < 3) LOAD_FRAGS((ks + 1) * 16, a[nxt], b[nxt]);
            #pragma unroll
            for (int mt = 0; mt < 4; mt++)
                #pragma unroll
                for (int nt = 0; nt < 8; nt++)
                    mma_f16(acc[mt][nt], a[cur][mt], b[cur][nt]);
        }
    }
#undef LOAD_FRAGS

    const int g = lane >> 2, tg = lane & 3;
    #pragma unroll
    for (int mt = 0; mt < 4; mt++)
        #pragma unroll
        for (int nt = 0; nt < 8; nt++) {
            int n = n0 + wn + nt * 8 + tg * 2;
            float bx = __ldg(bias + n), by = __ldg(bias + n + 1);
            #pragma unroll
            for (int hrow = 0; hrow < 2; hrow++) {
                int m = m0 + wm + mt * 16 + g + hrow * 8;
                float vx = acc[mt][nt][hrow * 2 + 0] + bx;
                float vy = acc[mt][nt][hrow * 2 + 1] + by;
                if (MODE == 0) {
                    int s   = n >> 10;
                    int rem = n & 1023;
                    int hh  = rem >> 6, dd = rem & 63;
                    int bi  = m >> 11, t = m & 2047;
                    if (s == 0) { vx *= 0.125f; vy *= 0.125f; }  // q pre-scale
                    __half* dst = (s == 0) ? g_q16 : (s == 1) ? g_k16 : g_v16;
                    size_t off = (((size_t)(bi * Hh + hh)) * Tt + t) * Dd + dd;
                    *(uint32_t*)(dst + off) = packh2(vx, vy);
                } else {
                    float2 o; o.x = vx; o.y = vy;
                    *(float2*)(Cout + (size_t)m * N + n) = o;
                }
            }
        }
}

// ---------------------------------------------------------------------------
// Flash attention, fp16 mma, cp.async 2-stage K/V pipeline,
// ONE __syncthreads per 64-key tile. (unchanged — protect 51.7%)
// ---------------------------------------------------------------------------
__global__ __launch_bounds__(128, 2) void attn_mma_kernel()
{
    extern __shared__ __half sm[];
    __half* Qs = sm;                            // 9216 halves
    constexpr uint32_t ST_K = 9216, ST_V = 13824;   // stage0 offsets (halves)
    constexpr uint32_t STAGE = 9216;                // halves per stage (K+V)

    const int tid = threadIdx.x, wid = tid >> 5, lane = tid & 31;
    const int qt = 15 - blockIdx.x;
    const int h = blockIdx.y, b = blockIdx.z;
    const int m0 = qt * 128;
    const size_t base = ((size_t)(b * Hh + h)) * Tt * Dd;
    const uint32_t smB = smem_u32(sm);

    #pragma unroll
    for (int i = 0; i < 8; i++) {
        int id = tid + i * 128;
        int r = id >> 3, c = id & 7;
        *(float4*)&Qs[r * 72 + c * 8] = *(const float4*)&g_q16[base + (size_t)(m0 + r) * Dd + c * 8];
    }

    const int wm = wid * 32;
    const int lr = lane & 15, lc = (lane >> 4) * 8;
    const int g = lane >> 2, tg = lane & 3;
    const uint32_t QB = smB;

    const int ldr = tid >> 3, ldc = tid & 7;    // 16 rows x 8 chunks
    auto load_tile = [&](int kt) {
        const uint32_t sb = smB + ((kt & 1) * STAGE + ST_K) * 2;
        #pragma unroll
        for (int i = 0; i < 4; i++) {
            int r = ldr + i * 16;
            uint32_t doff = (uint32_t)(r * 72 + ldc * 8) * 2;
            size_t src = base + (size_t)(kt * 64 + r) * Dd + ldc * 8;
            cpa16(sb + doff, &g_k16[src]);
            cpa16(sb + (ST_V - ST_K) * 2 + doff, &g_v16[src]);
        }
        CP_COMMIT();
    };

    float o[2][8][4];
    #pragma unroll
    for (int mt = 0; mt < 2; mt++)
        #pragma unroll
        for (int nt = 0; nt < 8; nt++)
            #pragma unroll
            for (int c = 0; c < 4; c++) o[mt][nt][c] = 0.f;
    float mrow[4] = {-1e30f, -1e30f, -1e30f, -1e30f};
    float lrow[4] = {0.f, 0.f, 0.f, 0.f};

    const int ntiles = 2 * qt + 2;
    load_tile(0);

    for (int kt = 0; kt < ntiles; kt++) {
        CP_WAIT(0);
        __syncthreads();
        if (kt + 1 < ntiles) load_tile(kt + 1);

        const uint32_t KB = smB + ((kt & 1) * STAGE + ST_K) * 2;
        const uint32_t VB = smB + ((kt & 1) * STAGE + ST_V) * 2;

        float s[2][8][4];
        #pragma unroll
        for (int mt = 0; mt < 2; mt++)
            #pragma unroll
            for (int nt = 0; nt < 8; nt++)
                #pragma unroll
                for (int c = 0; c < 4; c++) s[mt][nt][c] = 0.f;

        #pragma unroll
        for (int ks = 0; ks < 4; ks++) {
            uint32_t q[2][4];
            #pragma unroll
            for (int mt = 0; mt < 2; mt++) {
                uint32_t off = (uint32_t)((wm + mt * 16 + lr) * 72 + ks * 16 + lc) * 2;
                ldsm_x4(QB + off, q[mt][0], q[mt][1], q[mt][2], q[mt][3]);
            }
            uint32_t k[8][2];
            #pragma unroll
            for (int ng = 0; ng < 4; ng++) {
                uint32_t off = (uint32_t)((ng * 16 + lr) * 72 + ks * 16 + lc) * 2;
                uint32_t r0, r1, r2, r3;
                ldsm_x4(KB + off, r0, r1, r2, r3);
                k[ng*2+0][0] = r0; k[ng*2+0][1] = r2;
                k[ng*2+1][0] = r1; k[ng*2+1][1] = r3;
            }
            #pragma unroll
            for (int mt = 0; mt < 2; mt++)
                #pragma unroll
                for (int nt = 0; nt < 8; nt++)
                    mma_f16(s[mt][nt], q[mt], k[nt]);
        }

        if (kt >= 2 * qt) {
            #pragma unroll
            for (int mt = 0; mt < 2; mt++)
                #pragma unroll
                for (int nt = 0; nt < 8; nt++)
                    #pragma unroll
                    for (int c = 0; c < 4; c++) {
                        int row = m0 + wm + mt * 16 + (c >> 1) * 8 + g;
                        int kg  = kt * 64 + nt * 8 + tg * 2 + (c & 1);
                        if (kg > row) s[mt][nt][c] = -1e30f;
                    }
        }

        #pragma unroll
        for (int mt = 0; mt < 2; mt++)
            #pragma unroll
            for (int half = 0; half < 2; half++) {
                const int slot = mt * 2 + half;
                float mx = -1e30f;
                #pragma unroll
                for (int nt = 0; nt < 8; nt++)
                    mx = fmaxf(mx, fmaxf(s[mt][nt][half*2], s[mt][nt][half*2+1]));
                mx = fmaxf(mx, __shfl_xor_sync(0xffffffffu, mx, 1));
                mx = fmaxf(mx, __shfl_xor_sync(0xffffffffu, mx, 2));
                float Mn = fmaxf(mrow[slot], mx);
                float f = __expf(mrow[slot] - Mn);
                mrow[slot] = Mn;
                lrow[slot] *= f;
                float ps = 0.f;
                #pragma unroll
                for (int nt = 0; nt < 8; nt++) {
                    float p0 = __expf(s[mt][nt][half*2+0] - Mn);
                    float p1 = __expf(s[mt][nt][half*2+1] - Mn);
                    s[mt][nt][half*2+0] = p0;
                    s[mt][nt][half*2+1] = p1;
                    ps += p0 + p1;
                    o[mt][nt][half*2+0] *= f;
                    o[mt][nt][half*2+1] *= f;
                }
                ps += __shfl_xor_sync(0xffffffffu, ps, 1);
                ps += __shfl_xor_sync(0xffffffffu, ps, 2);
                lrow[slot] += ps;
            }

        #pragma unroll
        for (int ksp = 0; ksp < 4; ksp++) {
            uint32_t p[2][4];
            #pragma unroll
            for (int mt = 0; mt < 2; mt++) {
                p[mt][0] = packh2(s[mt][2*ksp+0][0], s[mt][2*ksp+0][1]);
                p[mt][1] = packh2(s[mt][2*ksp+0][2], s[mt][2*ksp+0][3]);
                p[mt][2] = packh2(s[mt][2*ksp+1][0], s[mt][2*ksp+1][1]);
                p[mt][3] = packh2(s[mt][2*ksp+1][2], s[mt][2*ksp+1][3]);
            }
            uint32_t v[8][2];
            #pragma unroll
            for (int ng = 0; ng < 4; ng++) {
                uint32_t off = (uint32_t)((ksp * 16 + lr) * 72 + ng * 16 + lc) * 2;
                uint32_t r0, r1, r2, r3;
                ldsm_x4_t(VB + off, r0, r1, r2, r3);
                v[ng*2+0][0] = r0; v[ng*2+0][1] = r1;
                v[ng*2+1][0] = r2; v[ng*2+1][1] = r3;
            }
            #pragma unroll
            for (int mt = 0; mt < 2; mt++)
                #pragma unroll
                for (int nt = 0; nt < 8; nt++)
                    mma_f16(o[mt][nt], p[mt], v[nt]);
        }
    }

    #pragma unroll
    for (int mt = 0; mt < 2; mt++)
        #pragma unroll
        for (int half = 0; half < 2; half++) {
            const float inv = 1.f / lrow[mt * 2 + half];
            int row = m0 + wm + mt * 16 + half * 8 + g;
            size_t doff = ((size_t)(b * Tt + row)) * Cc + h * Dd;
            #pragma unroll
            for (int nt = 0; nt < 8; nt++)
                *(uint32_t*)(g_ctx16 + doff + nt * 8 + tg * 2) =
                    packh2(o[mt][nt][half*2+0] * inv, o[mt][nt][half*2+1] * inv);
        }
}

// ---------------------------------------------------------------------------
extern "C" void kernel_launch(void* const* d_in, const int* in_sizes, int n_in,
                              void* d_out, int out_size)
{
    const float* x     = (const float*)d_in[0];
    const float* w_qkv = (const float*)d_in[1];
    const float* b_qkv = (const float*)d_in[2];
    const float* w_out = (const float*)d_in[3];
    const float* b_out = (const float*)d_in[4];
    float* out = (float*)d_out;

    constexpr int ATTN_SMEM = (9216 + 2 * 9216) * 2;    // 55296 B
    constexpr int TG_SMEM   = 2 * 2 * 128 * 72 * 2;     // 73728 B
    cudaFuncSetAttribute(attn_mma_kernel,
                         cudaFuncAttributeMaxDynamicSharedMemorySize, ATTN_SMEM);
    cudaFuncSetAttribute(tgemm_kernel<3072, 0>,
                         cudaFuncAttributeMaxDynamicSharedMemorySize, TG_SMEM);
    cudaFuncSetAttribute(tgemm_kernel<1024, 1>,
                         cudaFuncAttributeMaxDynamicSharedMemorySize, TG_SMEM);

    // 0) conversions
    conv_x_kernel<<<(size_t)NTOK * Cc / (256 * 4), 256>>>(x);
    {
        dim3 blk(32, 8);
        conv_w_kernel<0><<<dim3(3072 / 32, 1024 / 32), blk>>>(w_qkv);
        conv_w_kernel<1><<<dim3(1024 / 32, 1024 / 32), blk>>>(w_out);
    }
    // 1) QKV projection -> q/k/v fp16
    tgemm_kernel<3072, 0><<<dim3(3072 / 128, NTOK / 128), 128, TG_SMEM>>>(b_qkv, nullptr);
    // 2) flash attention -> ctx fp16
    attn_mma_kernel<<<dim3(16, Hh, Bb), 128, ATTN_SMEM>>>();
    // 3) output projection -> out (fp32)
    tgemm_kernel<1024, 1><<<dim3(1024 / 128, NTOK / 128), 128, TG_SMEM>>>(b_out, out);
}

// round 13
// speedup vs baseline: 10.3038x; 1.0003x over previous
#include <cuda_runtime.h>
#include <cuda_fp16.h>
#include <cstdint>

#define Bb 4
#define Tt 2048
#define Cc 1024
#define Hh 16
#define Dd 64
#define NTOK (Bb*Tt)   // 8192

// ---------------------------------------------------------------------------
// Scratch (__device__ globals)
// ---------------------------------------------------------------------------
__device__ __half g_x16[(size_t)NTOK*Cc];
__device__ __half g_ctx16[(size_t)NTOK*Cc];
__device__ __half g_q16[Bb*Hh*Tt*Dd], g_k16[Bb*Hh*Tt*Dd], g_v16[Bb*Hh*Tt*Dd];
__device__ __half g_wqkv16[3072*1024];
__device__ __half g_wout16[1024*1024];

// ---------------------------------------------------------------------------
// helpers
// ---------------------------------------------------------------------------
__device__ __forceinline__ uint32_t smem_u32(const void* p) {
    uint32_t a;
    asm("{ .reg .u64 t; cvta.to.shared.u64 t, %1; cvt.u32.u64 %0, t; }"
        : "=r"(a) : "l"(p));
    return a;
}
__device__ __forceinline__ void ldsm_x4(uint32_t addr, uint32_t& r0, uint32_t& r1,
                                        uint32_t& r2, uint32_t& r3) {
    asm volatile("ldmatrix.sync.aligned.m8n8.x4.shared.b16 {%0,%1,%2,%3}, [%4];"
                 : "=r"(r0), "=r"(r1), "=r"(r2), "=r"(r3) : "r"(addr));
}
__device__ __forceinline__ void ldsm_x4_t(uint32_t addr, uint32_t& r0, uint32_t& r1,
                                          uint32_t& r2, uint32_t& r3) {
    asm volatile("ldmatrix.sync.aligned.m8n8.x4.trans.shared.b16 {%0,%1,%2,%3}, [%4];"
                 : "=r"(r0), "=r"(r1), "=r"(r2), "=r"(r3) : "r"(addr));
}
__device__ __forceinline__ void mma_f16(float* d, const uint32_t* a, const uint32_t* b) {
    asm volatile(
        "mma.sync.aligned.m16n8k16.row.col.f32.f16.f16.f32 "
        "{%0,%1,%2,%3}, {%4,%5,%6,%7}, {%8,%9}, {%0,%1,%2,%3};"
        : "+f"(d[0]), "+f"(d[1]), "+f"(d[2]), "+f"(d[3])
        : "r"(a[0]), "r"(a[1]), "r"(a[2]), "r"(a[3]), "r"(b[0]), "r"(b[1]));
}
__device__ __forceinline__ uint32_t packh2(float x, float y) {
    __half2 h = __floats2half2_rn(x, y);
    return *(uint32_t*)&h;
}
// exp2 of a packed fp16x2 (one MUFU op for two values)
__device__ __forceinline__ uint32_t ex2_h2(uint32_t t) {
    uint32_t r;
    asm("ex2.approx.f16x2 %0, %1;" : "=r"(r) : "r"(t));
    return r;
}
__device__ __forceinline__ void cpa16(uint32_t dst, const void* src) {
    asm volatile("cp.async.cg.shared.global [%0], [%1], 16;" :: "r"(dst), "l"(src));
}
#define CP_COMMIT() asm volatile("cp.async.commit_group;" ::: "memory")
#define CP_WAIT(n)  asm volatile("cp.async.wait_group %0;" :: "n"(n) : "memory")

// ---------------------------------------------------------------------------
// x fp32 -> fp16
// ---------------------------------------------------------------------------
__global__ __launch_bounds__(256) void conv_x_kernel(const float* __restrict__ x)
{
    size_t i = ((size_t)blockIdx.x * 256 + threadIdx.x) * 4;
    float4 v = *(const float4*)(x + i);
    uint2 u;
    u.x = packh2(v.x, v.y);
    u.y = packh2(v.z, v.w);
    *(uint2*)(g_x16 + i) = u;
}

// ---------------------------------------------------------------------------
// Weight transpose + fp16: w[1024][N] -> Wt[N][1024]
// ---------------------------------------------------------------------------
template<int MODE>
__global__ __launch_bounds__(256) void conv_w_kernel(const float* __restrict__ w)
{
    constexpr int N = (MODE == 0) ? 3072 : 1024;
    __half* th = (MODE == 0) ? g_wqkv16 : g_wout16;
    __shared__ float tile[32][33];
    const int n0 = blockIdx.x * 32, k0 = blockIdx.y * 32;
    const int tx = threadIdx.x, ty = threadIdx.y;
    #pragma unroll
    for (int i = 0; i < 4; i++) {
        int k = ty + i * 8;
        tile[k][tx] = w[(size_t)(k0 + k) * N + n0 + tx];
    }
    __syncthreads();
    #pragma unroll
    for (int i = 0; i < 4; i++) {
        int r = ty + i * 8;
        th[(size_t)(n0 + r) * 1024 + k0 + tx] = __float2half_rn(tile[tx][r]);
    }
}

// ---------------------------------------------------------------------------
// fp16 HMMA GEMM: CTA 128x128, 4 warps (2Mx2N), warp tile 64x64.
// BK=64, 2-stage cp.async, ONE __syncthreads per chunk. (R12 form, unchanged)
// ---------------------------------------------------------------------------
template<int N, int MODE>
__global__ __launch_bounds__(128, 2) void tgemm_kernel(
    const float* __restrict__ bias, float* __restrict__ Cout)
{
    extern __shared__ __half sm[];
    constexpr int LDS = 72;
    constexpr uint32_t T_A = 0, T_B = 128*LDS;      // halves
    constexpr uint32_t STAGE = 2*128*LDS;           // halves per stage (18432)
    constexpr int NCH = 16;                          // 1024 / 64

    const __half* A = (MODE == 0) ? g_x16 : g_ctx16;
    const __half* W = (MODE == 0) ? g_wqkv16 : g_wout16;

    const int tid  = threadIdx.x;
    const int wid  = tid >> 5, lane = tid & 31;
    const int wm   = (wid & 1) * 64;
    const int wn   = (wid >> 1) * 64;
    const int lr   = lane & 15, lc = (lane >> 4) * 8;
    const int n0   = blockIdx.x * 128, m0 = blockIdx.y * 128;
    const uint32_t smB = smem_u32(sm);

    const int ldr = tid >> 3, ldc = tid & 7;        // 16 rows x 8 16B-chunks

    float acc[4][8][4];
    #pragma unroll
    for (int i = 0; i < 4; i++)
        #pragma unroll
        for (int j = 0; j < 8; j++)
            #pragma unroll
            for (int c = 0; c < 4; c++) acc[i][j][c] = 0.f;

    auto load_chunk = [&](int ch) {
        const int k0 = ch * 64;
        const uint32_t sb = smB + (ch & 1) * STAGE * 2;
        #pragma unroll
        for (int i = 0; i < 8; i++) {
            int r = ldr + i * 16;
            uint32_t doff = (uint32_t)(r * LDS + ldc * 8) * 2;
            cpa16(sb + T_A*2 + doff, A + (size_t)(m0 + r) * 1024 + k0 + ldc * 8);
            cpa16(sb + T_B*2 + doff, W + (size_t)(n0 + r) * 1024 + k0 + ldc * 8);
        }
        CP_COMMIT();
    };

    load_chunk(0);

    for (int ch = 0; ch < NCH; ch++) {
        CP_WAIT(0);
        __syncthreads();
        if (ch + 1 < NCH) load_chunk(ch + 1);

        const uint32_t sb = smB + (ch & 1) * STAGE * 2;
        const uint32_t aB = sb + T_A*2, bB = sb + T_B*2;

        #pragma unroll
        for (int ks = 0; ks < 4; ks++) {
            const int kk = ks * 16;
            uint32_t a[4][4], b[8][2];
            #pragma unroll
            for (int mt = 0; mt < 4; mt++) {
                uint32_t off = (uint32_t)((wm + mt * 16 + lr) * LDS + kk + lc) * 2;
                ldsm_x4(aB + off, a[mt][0], a[mt][1], a[mt][2], a[mt][3]);
            }
            #pragma unroll
            for (int np = 0; np < 4; np++) {
                uint32_t off = (uint32_t)((wn + np * 16 + lr) * LDS + kk + lc) * 2;
                uint32_t r0, r1, r2, r3;
                ldsm_x4(bB + off, r0, r1, r2, r3);
                b[np*2+0][0] = r0; b[np*2+0][1] = r2;
                b[np*2+1][0] = r1; b[np*2+1][1] = r3;
            }
            #pragma unroll
            for (int mt = 0; mt < 4; mt++)
                #pragma unroll
                for (int nt = 0; nt < 8; nt++)
                    mma_f16(acc[mt][nt], a[mt], b[nt]);
        }
    }

    const int g = lane >> 2, tg = lane & 3;
    #pragma unroll
    for (int mt = 0; mt < 4; mt++)
        #pragma unroll
        for (int nt = 0; nt < 8; nt++) {
            int n = n0 + wn + nt * 8 + tg * 2;
            float bx = __ldg(bias + n), by = __ldg(bias + n + 1);
            #pragma unroll
            for (int hrow = 0; hrow < 2; hrow++) {
                int m = m0 + wm + mt * 16 + g + hrow * 8;
                float vx = acc[mt][nt][hrow * 2 + 0] + bx;
                float vy = acc[mt][nt][hrow * 2 + 1] + by;
                if (MODE == 0) {
                    int s   = n >> 10;
                    int rem = n & 1023;
                    int hh  = rem >> 6, dd = rem & 63;
                    int bi  = m >> 11, t = m & 2047;
                    if (s == 0) { vx *= 0.125f; vy *= 0.125f; }  // q pre-scale
                    __half* dst = (s == 0) ? g_q16 : (s == 1) ? g_k16 : g_v16;
                    size_t off = (((size_t)(bi * Hh + hh)) * Tt + t) * Dd + dd;
                    *(uint32_t*)(dst + off) = packh2(vx, vy);
                } else {
                    float2 o; o.x = vx; o.y = vy;
                    *(float2*)(Cout + (size_t)m * N + n) = o;
                }
            }
        }
}

// ---------------------------------------------------------------------------
// Flash attention, fp16 mma, cp.async 2-stage K/V pipeline.
// NEW: softmax probs via ex2.approx.f16x2 — one MUFU per TWO probs, and the
// result is directly the fp16x2 P-fragment (no separate pack step).
// ---------------------------------------------------------------------------
__global__ __launch_bounds__(128, 2) void attn_mma_kernel()
{
    extern __shared__ __half sm[];
    __half* Qs = sm;                            // 9216 halves
    constexpr uint32_t ST_K = 9216, ST_V = 13824;   // stage0 offsets (halves)
    constexpr uint32_t STAGE = 9216;                // halves per stage (K+V)
    const float LOG2E = 1.4426950408889634f;

    const int tid = threadIdx.x, wid = tid >> 5, lane = tid & 31;
    const int qt = 15 - blockIdx.x;
    const int h = blockIdx.y, b = blockIdx.z;
    const int m0 = qt * 128;
    const size_t base = ((size_t)(b * Hh + h)) * Tt * Dd;
    const uint32_t smB = smem_u32(sm);

    #pragma unroll
    for (int i = 0; i < 8; i++) {
        int id = tid + i * 128;
        int r = id >> 3, c = id & 7;
        *(float4*)&Qs[r * 72 + c * 8] = *(const float4*)&g_q16[base + (size_t)(m0 + r) * Dd + c * 8];
    }

    const int wm = wid * 32;
    const int lr = lane & 15, lc = (lane >> 4) * 8;
    const int g = lane >> 2, tg = lane & 3;
    const uint32_t QB = smB;

    const int ldr = tid >> 3, ldc = tid & 7;    // 16 rows x 8 chunks
    auto load_tile = [&](int kt) {
        const uint32_t sb = smB + ((kt & 1) * STAGE + ST_K) * 2;
        #pragma unroll
        for (int i = 0; i < 4; i++) {
            int r = ldr + i * 16;
            uint32_t doff = (uint32_t)(r * 72 + ldc * 8) * 2;
            size_t src = base + (size_t)(kt * 64 + r) * Dd + ldc * 8;
            cpa16(sb + doff, &g_k16[src]);
            cpa16(sb + (ST_V - ST_K) * 2 + doff, &g_v16[src]);
        }
        CP_COMMIT();
    };

    float o[2][8][4];
    #pragma unroll
    for (int mt = 0; mt < 2; mt++)
        #pragma unroll
        for (int nt = 0; nt < 8; nt++)
            #pragma unroll
            for (int c = 0; c < 4; c++) o[mt][nt][c] = 0.f;
    float mrow[4] = {-1e30f, -1e30f, -1e30f, -1e30f};
    float lrow[4] = {0.f, 0.f, 0.f, 0.f};

    const int ntiles = 2 * qt + 2;
    load_tile(0);

    for (int kt = 0; kt < ntiles; kt++) {
        CP_WAIT(0);
        __syncthreads();
        if (kt + 1 < ntiles) load_tile(kt + 1);

        const uint32_t KB = smB + ((kt & 1) * STAGE + ST_K) * 2;
        const uint32_t VB = smB + ((kt & 1) * STAGE + ST_V) * 2;

        float s[2][8][4];
        #pragma unroll
        for (int mt = 0; mt < 2; mt++)
            #pragma unroll
            for (int nt = 0; nt < 8; nt++)
                #pragma unroll
                for (int c = 0; c < 4; c++) s[mt][nt][c] = 0.f;

        #pragma unroll
        for (int ks = 0; ks < 4; ks++) {
            uint32_t q[2][4];
            #pragma unroll
            for (int mt = 0; mt < 2; mt++) {
                uint32_t off = (uint32_t)((wm + mt * 16 + lr) * 72 + ks * 16 + lc) * 2;
                ldsm_x4(QB + off, q[mt][0], q[mt][1], q[mt][2], q[mt][3]);
            }
            uint32_t k[8][2];
            #pragma unroll
            for (int ng = 0; ng < 4; ng++) {
                uint32_t off = (uint32_t)((ng * 16 + lr) * 72 + ks * 16 + lc) * 2;
                uint32_t r0, r1, r2, r3;
                ldsm_x4(KB + off, r0, r1, r2, r3);
                k[ng*2+0][0] = r0; k[ng*2+0][1] = r2;
                k[ng*2+1][0] = r1; k[ng*2+1][1] = r3;
            }
            #pragma unroll
            for (int mt = 0; mt < 2; mt++)
                #pragma unroll
                for (int nt = 0; nt < 8; nt++)
                    mma_f16(s[mt][nt], q[mt], k[nt]);
        }

        if (kt >= 2 * qt) {
            #pragma unroll
            for (int mt = 0; mt < 2; mt++)
                #pragma unroll
                for (int nt = 0; nt < 8; nt++)
                    #pragma unroll
                    for (int c = 0; c < 4; c++) {
                        int row = m0 + wm + mt * 16 + (c >> 1) * 8 + g;
                        int kg  = kt * 64 + nt * 8 + tg * 2 + (c & 1);
                        if (kg > row) s[mt][nt][c] = -1e30f;
                    }
        }

        // online softmax: probs computed as fp16x2 via ex2.approx.f16x2
        uint32_t ph2[2][8][2];   // P fragments: [mt][nt][half] fp16x2
        #pragma unroll
        for (int mt = 0; mt < 2; mt++)
            #pragma unroll
            for (int half = 0; half < 2; half++) {
                const int slot = mt * 2 + half;
                float mx = -1e30f;
                #pragma unroll
                for (int nt = 0; nt < 8; nt++)
                    mx = fmaxf(mx, fmaxf(s[mt][nt][half*2], s[mt][nt][half*2+1]));
                mx = fmaxf(mx, __shfl_xor_sync(0xffffffffu, mx, 1));
                mx = fmaxf(mx, __shfl_xor_sync(0xffffffffu, mx, 2));
                float Mn = fmaxf(mrow[slot], mx);
                float f = __expf(mrow[slot] - Mn);
                mrow[slot] = Mn;
                lrow[slot] *= f;
                float ps = 0.f;
                #pragma unroll
                for (int nt = 0; nt < 8; nt++) {
                    float t0 = (s[mt][nt][half*2+0] - Mn) * LOG2E;
                    float t1 = (s[mt][nt][half*2+1] - Mn) * LOG2E;
                    uint32_t ph = ex2_h2(packh2(t0, t1));
                    ph2[mt][nt][half] = ph;
                    float2 pf = __half22float2(*(__half2*)&ph);
                    ps += pf.x + pf.y;
                    o[mt][nt][half*2+0] *= f;
                    o[mt][nt][half*2+1] *= f;
                }
                ps += __shfl_xor_sync(0xffffffffu, ps, 1);
                ps += __shfl_xor_sync(0xffffffffu, ps, 2);
                lrow[slot] += ps;
            }

        // PV: P fragments already fp16x2 in ph2
        #pragma unroll
        for (int ksp = 0; ksp < 4; ksp++) {
            uint32_t p[2][4];
            #pragma unroll
            for (int mt = 0; mt < 2; mt++) {
                p[mt][0] = ph2[mt][2*ksp+0][0];
                p[mt][1] = ph2[mt][2*ksp+0][1];
                p[mt][2] = ph2[mt][2*ksp+1][0];
                p[mt][3] = ph2[mt][2*ksp+1][1];
            }
            uint32_t v[8][2];
            #pragma unroll
            for (int ng = 0; ng < 4; ng++) {
                uint32_t off = (uint32_t)((ksp * 16 + lr) * 72 + ng * 16 + lc) * 2;
                uint32_t r0, r1, r2, r3;
                ldsm_x4_t(VB + off, r0, r1, r2, r3);
                v[ng*2+0][0] = r0; v[ng*2+0][1] = r1;
                v[ng*2+1][0] = r2; v[ng*2+1][1] = r3;
            }
            #pragma unroll
            for (int mt = 0; mt < 2; mt++)
                #pragma unroll
                for (int nt = 0; nt < 8; nt++)
                    mma_f16(o[mt][nt], p[mt], v[nt]);
        }
    }

    #pragma unroll
    for (int mt = 0; mt < 2; mt++)
        #pragma unroll
        for (int half = 0; half < 2; half++) {
            const float inv = 1.f / lrow[mt * 2 + half];
            int row = m0 + wm + mt * 16 + half * 8 + g;
            size_t doff = ((size_t)(b * Tt + row)) * Cc + h * Dd;
            #pragma unroll
            for (int nt = 0; nt < 8; nt++)
                *(uint32_t*)(g_ctx16 + doff + nt * 8 + tg * 2) =
                    packh2(o[mt][nt][half*2+0] * inv, o[mt][nt][half*2+1] * inv);
        }
}

// ---------------------------------------------------------------------------
extern "C" void kernel_launch(void* const* d_in, const int* in_sizes, int n_in,
                              void* d_out, int out_size)
{
    const float* x     = (const float*)d_in[0];
    const float* w_qkv = (const float*)d_in[1];
    const float* b_qkv = (const float*)d_in[2];
    const float* w_out = (const float*)d_in[3];
    const float* b_out = (const float*)d_in[4];
    float* out = (float*)d_out;

    constexpr int ATTN_SMEM = (9216 + 2 * 9216) * 2;    // 55296 B
    constexpr int TG_SMEM   = 2 * 2 * 128 * 72 * 2;     // 73728 B
    cudaFuncSetAttribute(attn_mma_kernel,
                         cudaFuncAttributeMaxDynamicSharedMemorySize, ATTN_SMEM);
    cudaFuncSetAttribute(tgemm_kernel<3072, 0>,
                         cudaFuncAttributeMaxDynamicSharedMemorySize, TG_SMEM);
    cudaFuncSetAttribute(tgemm_kernel<1024, 1>,
                         cudaFuncAttributeMaxDynamicSharedMemorySize, TG_SMEM);

    // 0) conversions
    conv_x_kernel<<<(size_t)NTOK * Cc / (256 * 4), 256>>>(x);
    {
        dim3 blk(32, 8);
        conv_w_kernel<0><<<dim3(3072 / 32, 1024 / 32), blk>>>(w_qkv);
        conv_w_kernel<1><<<dim3(1024 / 32, 1024 / 32), blk>>>(w_out);
    }
    // 1) QKV projection -> q/k/v fp16
    tgemm_kernel<3072, 0><<<dim3(3072 / 128, NTOK / 128), 128, TG_SMEM>>>(b_qkv, nullptr);
    // 2) flash attention -> ctx fp16
    attn_mma_kernel<<<dim3(16, Hh, Bb), 128, ATTN_SMEM>>>();
    // 3) output projection -> out (fp32)
    tgemm_kernel<1024, 1><<<dim3(1024 / 128, NTOK / 128), 128, TG_SMEM>>>(b_out, out);
}